// round 1
// baseline (speedup 1.0000x reference)
#include <cuda_runtime.h>
#include <math.h>

// Problem constants
#define CB  2
#define CS  2048
#define CE  1024
#define CH  16
#define CHD 64

// Scratch (no cudaMalloc allowed)
__device__ float g_qkv[(size_t)CB * CS * 3 * CE];   // [B,S,3,H,HD] = [B,S,3E]
__device__ float g_ctx[(size_t)CB * CS * CE];       // [B,S,E]

// ---------------------------------------------------------------------------
// SGEMM: C[M,N] = A[M,K] * W[N,K]^T + bias[N]
// Both A and W are K-major (contiguous along K) -> identical load paths.
// 128x128 tile, BK=8, 256 threads, 8x8 per thread (split 4+4 fragments).
// ---------------------------------------------------------------------------
__global__ __launch_bounds__(256) void sgemm_tn_bias(
    const float* __restrict__ A,
    const float* __restrict__ W,
    const float* __restrict__ bias,
    float* __restrict__ C,
    int M, int N, int K)
{
    __shared__ float As[8][132];
    __shared__ float Bs[8][132];

    const int t  = threadIdx.x;
    const int tx = t & 15;
    const int ty = t >> 4;
    const int m0 = blockIdx.y * 128;
    const int n0 = blockIdx.x * 128;

    const int lr = t >> 1;          // load row 0..127
    const int lc = (t & 1) * 4;     // 0 or 4 (k offset)

    const float* Ap = A + (size_t)(m0 + lr) * K + lc;
    const float* Wp = W + (size_t)(n0 + lr) * K + lc;

    float acc[8][8];
#pragma unroll
    for (int i = 0; i < 8; i++)
#pragma unroll
        for (int j = 0; j < 8; j++) acc[i][j] = 0.0f;

    for (int k0 = 0; k0 < K; k0 += 8) {
        float4 av = *(const float4*)(Ap + k0);
        float4 wv = *(const float4*)(Wp + k0);
        __syncthreads();
        As[lc + 0][lr] = av.x; As[lc + 1][lr] = av.y;
        As[lc + 2][lr] = av.z; As[lc + 3][lr] = av.w;
        Bs[lc + 0][lr] = wv.x; Bs[lc + 1][lr] = wv.y;
        Bs[lc + 2][lr] = wv.z; Bs[lc + 3][lr] = wv.w;
        __syncthreads();
#pragma unroll
        for (int k = 0; k < 8; k++) {
            float a[8], b[8];
            *(float4*)(a)     = *(const float4*)&As[k][ty * 4];
            *(float4*)(a + 4) = *(const float4*)&As[k][64 + ty * 4];
            *(float4*)(b)     = *(const float4*)&Bs[k][tx * 4];
            *(float4*)(b + 4) = *(const float4*)&Bs[k][64 + tx * 4];
#pragma unroll
            for (int i = 0; i < 8; i++)
#pragma unroll
                for (int j = 0; j < 8; j++)
                    acc[i][j] += a[i] * b[j];
        }
    }

    // Epilogue with bias
    float b0[4], b1[4];
#pragma unroll
    for (int j = 0; j < 4; j++) {
        b0[j] = bias[n0 + tx * 4 + j];
        b1[j] = bias[n0 + 64 + tx * 4 + j];
    }
#pragma unroll
    for (int i = 0; i < 8; i++) {
        int row = m0 + ((i < 4) ? (ty * 4 + i) : (64 + ty * 4 + (i - 4)));
        float4 o0 = make_float4(acc[i][0] + b0[0], acc[i][1] + b0[1],
                                acc[i][2] + b0[2], acc[i][3] + b0[3]);
        float4 o1 = make_float4(acc[i][4] + b1[0], acc[i][5] + b1[1],
                                acc[i][6] + b1[2], acc[i][7] + b1[3]);
        *(float4*)(C + (size_t)row * N + n0 + tx * 4)      = o0;
        *(float4*)(C + (size_t)row * N + n0 + 64 + tx * 4) = o1;
    }
}

// ---------------------------------------------------------------------------
// Flash attention (fp32). One CTA per (64-query tile, b, h).
// Q,K stored d-major in smem (transposed); V row-major; P staged in smem.
// 256 threads = 16x16, each owns a 4x4 tile of the 64x64 score block.
// ---------------------------------------------------------------------------
#define AS 68   // smem row stride (floats); multiple of 4 for float4 alignment
#define ATTN_SMEM (4 * 64 * AS * (int)sizeof(float))

__global__ __launch_bounds__(256) void flash_attn_fp32(
    const float* __restrict__ qkv,   // [B,S,3E]
    float* __restrict__ ctx)         // [B,S,E]
{
    extern __shared__ float sm[];
    float* Qt = sm;                  // [d=64][AS] (col = q row)
    float* Kt = Qt + 64 * AS;        // [d=64][AS] (col = key row)
    float* Vs = Kt + 64 * AS;        // [key=64][AS] (col = d)
    float* Ps = Vs + 64 * AS;        // [qrow=64][AS] (col = key)

    const int t  = threadIdx.x;
    const int tx = t & 15;
    const int ty = t >> 4;
    const int q0 = blockIdx.x * 64;
    const int bh = blockIdx.y;
    const int b  = bh >> 4;          // / CH
    const int h  = bh & 15;

    const size_t rowstride = 3 * CE; // per (b,s) stride
    const float* qbase = qkv + (size_t)b * CS * rowstride + h * CHD;
    const float* kbase = qbase + CE;
    const float* vbase = qbase + 2 * CE;

    // Load Q tile transposed, pre-scaled by 1/sqrt(HD) = 0.125
#pragma unroll
    for (int it = 0; it < 4; it++) {
        int idx = t + it * 256;       // 0..1023 float4 slots
        int row = idx >> 4;           // 0..63
        int c4  = (idx & 15) << 2;    // 0..60
        float4 v = *(const float4*)(qbase + (size_t)(q0 + row) * rowstride + c4);
        Qt[(c4 + 0) * AS + row] = v.x * 0.125f;
        Qt[(c4 + 1) * AS + row] = v.y * 0.125f;
        Qt[(c4 + 2) * AS + row] = v.z * 0.125f;
        Qt[(c4 + 3) * AS + row] = v.w * 0.125f;
    }

    float m_i[4], l_i[4], o[4][4];
#pragma unroll
    for (int i = 0; i < 4; i++) {
        m_i[i] = -3.0e38f;
        l_i[i] = 0.0f;
#pragma unroll
        for (int j = 0; j < 4; j++) o[i][j] = 0.0f;
    }

    for (int kt = 0; kt < CS / 64; kt++) {
        const int k0 = kt * 64;
        __syncthreads();   // prev PV reads of Vs/Ps done; Qt stores visible on 1st iter
#pragma unroll
        for (int it = 0; it < 4; it++) {
            int idx = t + it * 256;
            int row = idx >> 4;
            int c4  = (idx & 15) << 2;
            const float* kp = kbase + (size_t)(k0 + row) * rowstride + c4;
            const float* vp = vbase + (size_t)(k0 + row) * rowstride + c4;
            float4 kv = *(const float4*)kp;
            float4 vv = *(const float4*)vp;
            Kt[(c4 + 0) * AS + row] = kv.x;
            Kt[(c4 + 1) * AS + row] = kv.y;
            Kt[(c4 + 2) * AS + row] = kv.z;
            Kt[(c4 + 3) * AS + row] = kv.w;
            *(float4*)&Vs[row * AS + c4] = vv;
        }
        __syncthreads();

        // S = (Q * scale) K^T : 64x64x64
        float s[4][4];
#pragma unroll
        for (int i = 0; i < 4; i++)
#pragma unroll
            for (int j = 0; j < 4; j++) s[i][j] = 0.0f;

#pragma unroll 16
        for (int d = 0; d < 64; d++) {
            float4 a  = *(const float4*)&Qt[d * AS + ty * 4];
            float4 bb = *(const float4*)&Kt[d * AS + tx * 4];
            s[0][0] += a.x * bb.x; s[0][1] += a.x * bb.y; s[0][2] += a.x * bb.z; s[0][3] += a.x * bb.w;
            s[1][0] += a.y * bb.x; s[1][1] += a.y * bb.y; s[1][2] += a.y * bb.z; s[1][3] += a.y * bb.w;
            s[2][0] += a.z * bb.x; s[2][1] += a.z * bb.y; s[2][2] += a.z * bb.z; s[2][3] += a.z * bb.w;
            s[3][0] += a.w * bb.x; s[3][1] += a.w * bb.y; s[3][2] += a.w * bb.z; s[3][3] += a.w * bb.w;
        }

        // Online softmax: 16 lanes per row live in one half-warp (xor<=8 stays inside)
#pragma unroll
        for (int i = 0; i < 4; i++) {
            float mx = fmaxf(fmaxf(s[i][0], s[i][1]), fmaxf(s[i][2], s[i][3]));
#pragma unroll
            for (int off = 8; off; off >>= 1)
                mx = fmaxf(mx, __shfl_xor_sync(0xffffffffu, mx, off));
            float mnew = fmaxf(m_i[i], mx);
            float corr = __expf(m_i[i] - mnew);
            float ps = 0.0f;
#pragma unroll
            for (int j = 0; j < 4; j++) {
                float p = __expf(s[i][j] - mnew);
                s[i][j] = p;
                ps += p;
            }
#pragma unroll
            for (int off = 8; off; off >>= 1)
                ps += __shfl_xor_sync(0xffffffffu, ps, off);
            l_i[i] = l_i[i] * corr + ps;
            m_i[i] = mnew;
            o[i][0] *= corr; o[i][1] *= corr; o[i][2] *= corr; o[i][3] *= corr;
            *(float4*)&Ps[(ty * 4 + i) * AS + tx * 4] =
                make_float4(s[i][0], s[i][1], s[i][2], s[i][3]);
        }
        __syncthreads();

        // O += P * V : 64x64x64
#pragma unroll 16
        for (int jp = 0; jp < 64; jp++) {
            float4 vv = *(const float4*)&Vs[jp * AS + tx * 4];
            float p0 = Ps[(ty * 4 + 0) * AS + jp];
            float p1 = Ps[(ty * 4 + 1) * AS + jp];
            float p2 = Ps[(ty * 4 + 2) * AS + jp];
            float p3 = Ps[(ty * 4 + 3) * AS + jp];
            o[0][0] += p0 * vv.x; o[0][1] += p0 * vv.y; o[0][2] += p0 * vv.z; o[0][3] += p0 * vv.w;
            o[1][0] += p1 * vv.x; o[1][1] += p1 * vv.y; o[1][2] += p1 * vv.z; o[1][3] += p1 * vv.w;
            o[2][0] += p2 * vv.x; o[2][1] += p2 * vv.y; o[2][2] += p2 * vv.z; o[2][3] += p2 * vv.w;
            o[3][0] += p3 * vv.x; o[3][1] += p3 * vv.y; o[3][2] += p3 * vv.z; o[3][3] += p3 * vv.w;
        }
    }

    // Normalize and write ctx[b, q0+row, h*64 + d]
#pragma unroll
    for (int i = 0; i < 4; i++) {
        float inv = 1.0f / l_i[i];
        int row = q0 + ty * 4 + i;
        float4 r = make_float4(o[i][0] * inv, o[i][1] * inv,
                               o[i][2] * inv, o[i][3] * inv);
        *(float4*)(ctx + ((size_t)b * CS + row) * CE + h * CHD + tx * 4) = r;
    }
}

// ---------------------------------------------------------------------------
extern "C" void kernel_launch(void* const* d_in, const int* in_sizes, int n_in,
                              void* d_out, int out_size)
{
    const float* query = (const float*)d_in[0];
    // d_in[1]=key, d_in[2]=value are ignored by the module (QKV all from query)
    const float* qkv_w = (const float*)d_in[3];
    const float* qkv_b = (const float*)d_in[4];
    const float* out_w = (const float*)d_in[5];
    const float* out_b = (const float*)d_in[6];
    float* out = (float*)d_out;

    float *qkv_buf = nullptr, *ctx_buf = nullptr;
    cudaGetSymbolAddress((void**)&qkv_buf, g_qkv);
    cudaGetSymbolAddress((void**)&ctx_buf, g_ctx);

    cudaFuncSetAttribute(flash_attn_fp32,
                         cudaFuncAttributeMaxDynamicSharedMemorySize, ATTN_SMEM);

    // 1) QKV projection: [4096,1024] x [3072,1024]^T -> [4096,3072]
    sgemm_tn_bias<<<dim3(3 * CE / 128, CB * CS / 128), 256>>>(
        query, qkv_w, qkv_b, qkv_buf, CB * CS, 3 * CE, CE);

    // 2) Attention: 32 q-tiles x (B*H)=32
    flash_attn_fp32<<<dim3(CS / 64, CB * CH), 256, ATTN_SMEM>>>(qkv_buf, ctx_buf);

    // 3) Output projection: [4096,1024] x [1024,1024]^T -> [4096,1024]
    sgemm_tn_bias<<<dim3(CE / 128, CB * CS / 128), 256>>>(
        ctx_buf, out_w, out_b, out, CB * CS, CE, CE);
}

// round 4
// speedup vs baseline: 2.2902x; 2.2902x over previous
#include <cuda_runtime.h>
#include <cstdint>
#include <math.h>

// Problem constants
#define CB  2
#define CS  2048
#define CE  1024
#define CH  16
#define CHD 64

// Scratch (no cudaMalloc allowed)
__device__ float g_qkv[(size_t)CB * CS * 3 * CE];   // [B,S,3E]
__device__ float g_ctx[(size_t)CB * CS * CE];       // [B,S,E]

// ---------------------------------------------------------------------------
// tf32 helpers (all plain sm_80-era PTX; no 'a'-suffix features)
// ---------------------------------------------------------------------------
__device__ __forceinline__ uint32_t f2tf(float x) {
    uint32_t r;
    asm("cvt.rna.tf32.f32 %0, %1;" : "=r"(r) : "f"(x));
    return r;
}

// D += A(16x8) * B(8x8), tf32 inputs, fp32 accum.
__device__ __forceinline__ void mma8(float* d, const uint32_t* a, const uint32_t* b) {
    asm volatile(
        "mma.sync.aligned.m16n8k8.row.col.f32.tf32.tf32.f32 "
        "{%0,%1,%2,%3}, {%4,%5,%6,%7}, {%8,%9}, {%0,%1,%2,%3};"
        : "+f"(d[0]), "+f"(d[1]), "+f"(d[2]), "+f"(d[3])
        : "r"(a[0]), "r"(a[1]), "r"(a[2]), "r"(a[3]), "r"(b[0]), "r"(b[1]));
}

// ===========================================================================
// GEMM: C[M,N] = A[M,K] * W[N,K]^T + bias[N]    (tf32 mma.sync)
// 128x128 CTA tile, BK=32, 256 threads (8 warps, 2m x 4n), warp tile 64x32.
// ===========================================================================
#define GPAD 36

__global__ __launch_bounds__(256) void mma_gemm_bias(
    const float* __restrict__ A, const float* __restrict__ W,
    const float* __restrict__ bias, float* __restrict__ C,
    int M, int N, int K)
{
    __shared__ uint32_t As[128][GPAD];
    __shared__ uint32_t Bs[128][GPAD];

    const int t    = threadIdx.x;
    const int wid  = t >> 5;
    const int lane = t & 31;
    const int g    = lane >> 2;
    const int tig  = lane & 3;
    const int wm   = (wid & 1) * 64;
    const int wn   = (wid >> 1) * 32;
    const int m0   = blockIdx.y * 128;
    const int n0   = blockIdx.x * 128;

    const int lr = t >> 1;
    const int lc = (t & 1) * 16;
    const float* Ap = A + (size_t)(m0 + lr) * K + lc;
    const float* Wp = W + (size_t)(n0 + lr) * K + lc;

    float acc[4][4][4];
#pragma unroll
    for (int mf = 0; mf < 4; mf++)
#pragma unroll
        for (int nf = 0; nf < 4; nf++)
#pragma unroll
            for (int r = 0; r < 4; r++) acc[mf][nf][r] = 0.0f;

    const int NC = K >> 5;
    for (int kc = 0; kc < NC; kc++) {
        float4 av[4], wv[4];
#pragma unroll
        for (int i = 0; i < 4; i++) {
            av[i] = *(const float4*)(Ap + kc * 32 + i * 4);
            wv[i] = *(const float4*)(Wp + kc * 32 + i * 4);
        }
        __syncthreads();
#pragma unroll
        for (int i = 0; i < 4; i++) {
            As[lr][lc + i * 4 + 0] = f2tf(av[i].x);
            As[lr][lc + i * 4 + 1] = f2tf(av[i].y);
            As[lr][lc + i * 4 + 2] = f2tf(av[i].z);
            As[lr][lc + i * 4 + 3] = f2tf(av[i].w);
            Bs[lr][lc + i * 4 + 0] = f2tf(wv[i].x);
            Bs[lr][lc + i * 4 + 1] = f2tf(wv[i].y);
            Bs[lr][lc + i * 4 + 2] = f2tf(wv[i].z);
            Bs[lr][lc + i * 4 + 3] = f2tf(wv[i].w);
        }
        __syncthreads();

#pragma unroll
        for (int kk = 0; kk < 4; kk++) {
            uint32_t a[4][4];
#pragma unroll
            for (int mf = 0; mf < 4; mf++) {
                int m = wm + mf * 16;
                a[mf][0] = As[m + g    ][kk * 8 + tig];
                a[mf][1] = As[m + g + 8][kk * 8 + tig];
                a[mf][2] = As[m + g    ][kk * 8 + tig + 4];
                a[mf][3] = As[m + g + 8][kk * 8 + tig + 4];
            }
#pragma unroll
            for (int nf = 0; nf < 4; nf++) {
                uint32_t b[2];
                int n = wn + nf * 8;
                b[0] = Bs[n + g][kk * 8 + tig];
                b[1] = Bs[n + g][kk * 8 + tig + 4];
#pragma unroll
                for (int mf = 0; mf < 4; mf++)
                    mma8(acc[mf][nf], a[mf], b);
            }
        }
    }

    // Epilogue with bias. c0,c1 = row g cols (2tig,2tig+1); c2,c3 = row g+8.
#pragma unroll
    for (int mf = 0; mf < 4; mf++) {
#pragma unroll
        for (int nf = 0; nf < 4; nf++) {
            int row = m0 + wm + mf * 16 + g;
            int col = n0 + wn + nf * 8 + 2 * tig;
            float2 bv = *(const float2*)(bias + col);
            float2 o0 = make_float2(acc[mf][nf][0] + bv.x, acc[mf][nf][1] + bv.y);
            float2 o1 = make_float2(acc[mf][nf][2] + bv.x, acc[mf][nf][3] + bv.y);
            *(float2*)(C + (size_t)row * N + col)       = o0;
            *(float2*)(C + (size_t)(row + 8) * N + col) = o1;
        }
    }
}

// ===========================================================================
// Flash attention, tf32 mma.sync. One CTA per (64-query tile, b, h).
// 128 threads = 4 warps; each warp owns 16 query rows (one m-frag).
// S tile 64(q) x 64(keys) per block; softmax in registers (known C mapping);
// P staged through smem (per-warp rows, __syncwarp only) for the PV GEMM.
// ===========================================================================
#define APAD 68
#define ATTN_SMEM (4 * 64 * APAD * (int)sizeof(uint32_t))

__global__ __launch_bounds__(128) void flash_attn_tf32(
    const float* __restrict__ qkv,   // [B,S,3E]
    float* __restrict__ ctx)         // [B,S,E]
{
    extern __shared__ uint32_t smu[];
    uint32_t (*Qs)[APAD] = (uint32_t(*)[APAD])smu;           // [qrow][d]   tf32
    uint32_t (*Ks)[APAD] = Qs + 64;                           // [key][d]    tf32
    uint32_t (*Vt)[APAD] = Ks + 64;                           // [d][key]    tf32
    uint32_t (*Ps)[APAD] = Vt + 64;                           // [qrow][key] tf32

    const int t    = threadIdx.x;
    const int wid  = t >> 5;
    const int lane = t & 31;
    const int g    = lane >> 2;
    const int tig  = lane & 3;
    const int wm   = wid * 16;

    const int q0 = blockIdx.x * 64;
    const int bh = blockIdx.y;
    const int b  = bh >> 4;
    const int h  = bh & 15;

    const size_t rowstride = 3 * CE;
    const float* qbase = qkv + (size_t)b * CS * rowstride + h * CHD;
    const float* kbase = qbase + CE;
    const float* vbase = qbase + 2 * CE;

    // Load Q tile (pre-scaled by 1/sqrt(64)=0.125, tf32). 64x64 floats.
    {
        int row = t >> 1;
        int c0  = (t & 1) * 32;
#pragma unroll
        for (int i = 0; i < 8; i++) {
            float4 v = *(const float4*)(qbase + (size_t)(q0 + row) * rowstride + c0 + i * 4);
            Qs[row][c0 + i * 4 + 0] = f2tf(v.x * 0.125f);
            Qs[row][c0 + i * 4 + 1] = f2tf(v.y * 0.125f);
            Qs[row][c0 + i * 4 + 2] = f2tf(v.z * 0.125f);
            Qs[row][c0 + i * 4 + 3] = f2tf(v.w * 0.125f);
        }
    }

    float m_i[2] = {-3.0e38f, -3.0e38f};
    float l_i[2] = {0.0f, 0.0f};
    float o[8][4];
#pragma unroll
    for (int nf = 0; nf < 8; nf++)
#pragma unroll
        for (int r = 0; r < 4; r++) o[nf][r] = 0.0f;

    for (int kt = 0; kt < CS / 64; kt++) {
        const int k0 = kt * 64;
        __syncthreads();   // prev block's PV reads of Ks/Vt done (covers Qs on iter 0)

        // Load K (direct) and V (transposed) tiles, tf32.
#pragma unroll
        for (int it = 0; it < 8; it++) {
            int idx = t + it * 128;
            int row = idx >> 4;            // 0..63
            int c4  = (idx & 15) << 2;     // 0..60
            float4 kv = *(const float4*)(kbase + (size_t)(k0 + row) * rowstride + c4);
            float4 vv = *(const float4*)(vbase + (size_t)(k0 + row) * rowstride + c4);
            Ks[row][c4 + 0] = f2tf(kv.x);
            Ks[row][c4 + 1] = f2tf(kv.y);
            Ks[row][c4 + 2] = f2tf(kv.z);
            Ks[row][c4 + 3] = f2tf(kv.w);
            Vt[c4 + 0][row] = f2tf(vv.x);
            Vt[c4 + 1][row] = f2tf(vv.y);
            Vt[c4 + 2][row] = f2tf(vv.z);
            Vt[c4 + 3][row] = f2tf(vv.w);
        }
        __syncthreads();

        // ---- S = Q K^T (64x64x64) ----
        float s[8][4];
#pragma unroll
        for (int nf = 0; nf < 8; nf++)
#pragma unroll
            for (int r = 0; r < 4; r++) s[nf][r] = 0.0f;

#pragma unroll
        for (int kk = 0; kk < 8; kk++) {
            uint32_t a[4];
            a[0] = Qs[wm + g    ][kk * 8 + tig];
            a[1] = Qs[wm + g + 8][kk * 8 + tig];
            a[2] = Qs[wm + g    ][kk * 8 + tig + 4];
            a[3] = Qs[wm + g + 8][kk * 8 + tig + 4];
#pragma unroll
            for (int nf = 0; nf < 8; nf++) {
                uint32_t bb[2];
                bb[0] = Ks[nf * 8 + g][kk * 8 + tig];
                bb[1] = Ks[nf * 8 + g][kk * 8 + tig + 4];
                mma8(s[nf], a, bb);
            }
        }

        // ---- online softmax (thread owns rows g and g+8; 4 tig lanes/row) ----
        float mx0 = -3.0e38f, mx1 = -3.0e38f;
#pragma unroll
        for (int nf = 0; nf < 8; nf++) {
            mx0 = fmaxf(mx0, fmaxf(s[nf][0], s[nf][1]));
            mx1 = fmaxf(mx1, fmaxf(s[nf][2], s[nf][3]));
        }
        mx0 = fmaxf(mx0, __shfl_xor_sync(0xffffffffu, mx0, 1));
        mx0 = fmaxf(mx0, __shfl_xor_sync(0xffffffffu, mx0, 2));
        mx1 = fmaxf(mx1, __shfl_xor_sync(0xffffffffu, mx1, 1));
        mx1 = fmaxf(mx1, __shfl_xor_sync(0xffffffffu, mx1, 2));

        float mn0 = fmaxf(m_i[0], mx0);
        float mn1 = fmaxf(m_i[1], mx1);
        float corr0 = __expf(m_i[0] - mn0);
        float corr1 = __expf(m_i[1] - mn1);
        float sum0 = 0.0f, sum1 = 0.0f;
#pragma unroll
        for (int nf = 0; nf < 8; nf++) {
            s[nf][0] = __expf(s[nf][0] - mn0);
            s[nf][1] = __expf(s[nf][1] - mn0);
            s[nf][2] = __expf(s[nf][2] - mn1);
            s[nf][3] = __expf(s[nf][3] - mn1);
            sum0 += s[nf][0] + s[nf][1];
            sum1 += s[nf][2] + s[nf][3];
        }
        sum0 += __shfl_xor_sync(0xffffffffu, sum0, 1);
        sum0 += __shfl_xor_sync(0xffffffffu, sum0, 2);
        sum1 += __shfl_xor_sync(0xffffffffu, sum1, 1);
        sum1 += __shfl_xor_sync(0xffffffffu, sum1, 2);

        l_i[0] = l_i[0] * corr0 + sum0;
        l_i[1] = l_i[1] * corr1 + sum1;
        m_i[0] = mn0;
        m_i[1] = mn1;
#pragma unroll
        for (int nf = 0; nf < 8; nf++) {
            o[nf][0] *= corr0; o[nf][1] *= corr0;
            o[nf][2] *= corr1; o[nf][3] *= corr1;
        }

        // Store P (tf32) to per-warp rows of Ps; C-frag -> A-frag relayout.
#pragma unroll
        for (int nf = 0; nf < 8; nf++) {
            uint2 p0 = make_uint2(f2tf(s[nf][0]), f2tf(s[nf][1]));
            uint2 p1 = make_uint2(f2tf(s[nf][2]), f2tf(s[nf][3]));
            *(uint2*)&Ps[wm + g    ][nf * 8 + 2 * tig] = p0;
            *(uint2*)&Ps[wm + g + 8][nf * 8 + 2 * tig] = p1;
        }
        __syncwarp();   // warp reads only its own 16 rows

        // ---- O += P V (64x64x64) ----
#pragma unroll
        for (int kk = 0; kk < 8; kk++) {
            uint32_t a[4];
            a[0] = Ps[wm + g    ][kk * 8 + tig];
            a[1] = Ps[wm + g + 8][kk * 8 + tig];
            a[2] = Ps[wm + g    ][kk * 8 + tig + 4];
            a[3] = Ps[wm + g + 8][kk * 8 + tig + 4];
#pragma unroll
            for (int nf = 0; nf < 8; nf++) {
                uint32_t bb[2];
                bb[0] = Vt[nf * 8 + g][kk * 8 + tig];
                bb[1] = Vt[nf * 8 + g][kk * 8 + tig + 4];
                mma8(o[nf], a, bb);
            }
        }
    }

    // Normalize + write ctx[b, q0+row, h*64 + col]
    float inv0 = 1.0f / l_i[0];
    float inv1 = 1.0f / l_i[1];
#pragma unroll
    for (int nf = 0; nf < 8; nf++) {
        int row = q0 + wm + g;
        int col = h * CHD + nf * 8 + 2 * tig;
        float2 r0 = make_float2(o[nf][0] * inv0, o[nf][1] * inv0);
        float2 r1 = make_float2(o[nf][2] * inv1, o[nf][3] * inv1);
        *(float2*)(ctx + ((size_t)b * CS + row)     * CE + col) = r0;
        *(float2*)(ctx + ((size_t)b * CS + row + 8) * CE + col) = r1;
    }
}

// ---------------------------------------------------------------------------
extern "C" void kernel_launch(void* const* d_in, const int* in_sizes, int n_in,
                              void* d_out, int out_size)
{
    const float* query = (const float*)d_in[0];
    const float* qkv_w = (const float*)d_in[3];
    const float* qkv_b = (const float*)d_in[4];
    const float* out_w = (const float*)d_in[5];
    const float* out_b = (const float*)d_in[6];
    float* out = (float*)d_out;

    float *qkv_buf = nullptr, *ctx_buf = nullptr;
    cudaGetSymbolAddress((void**)&qkv_buf, g_qkv);
    cudaGetSymbolAddress((void**)&ctx_buf, g_ctx);

    cudaFuncSetAttribute(flash_attn_tf32,
                         cudaFuncAttributeMaxDynamicSharedMemorySize, ATTN_SMEM);

    // 1) QKV projection: [4096,1024] x [3072,1024]^T -> [4096,3072]
    mma_gemm_bias<<<dim3(3 * CE / 128, CB * CS / 128), 256>>>(
        query, qkv_w, qkv_b, qkv_buf, CB * CS, 3 * CE, CE);

    // 2) Attention: 32 q-tiles x (B*H)=32
    flash_attn_tf32<<<dim3(CS / 64, CB * CH), 128, ATTN_SMEM>>>(qkv_buf, ctx_buf);

    // 3) Output projection: [4096,1024] x [1024,1024]^T -> [4096,1024]
    mma_gemm_bias<<<dim3(CE / 128, CB * CS / 128), 256>>>(
        ctx_buf, out_w, out_b, out, CB * CS, CE, CE);
}

// round 5
// speedup vs baseline: 3.0297x; 1.3229x over previous
#include <cuda_runtime.h>
#include <cstdint>
#include <math.h>

// Problem constants
#define CB  2
#define CS  2048
#define CE  1024
#define CH  16
#define CHD 64

// Scratch (no cudaMalloc allowed)
__device__ float g_qkv[(size_t)CB * CS * 3 * CE];   // [B,S,3E]
__device__ float g_ctx[(size_t)CB * CS * CE];       // [B,S,E]

// ---------------------------------------------------------------------------
// tf32 helpers (plain sm_80-era PTX; no 'a'-suffix features)
// ---------------------------------------------------------------------------
__device__ __forceinline__ uint32_t f2tf(float x) {
    uint32_t r;
    asm("cvt.rna.tf32.f32 %0, %1;" : "=r"(r) : "f"(x));
    return r;
}

// D += A(16x8) * B(8x8), tf32 inputs, fp32 accum.
__device__ __forceinline__ void mma8(float* d, const uint32_t* a, const uint32_t* b) {
    asm volatile(
        "mma.sync.aligned.m16n8k8.row.col.f32.tf32.tf32.f32 "
        "{%0,%1,%2,%3}, {%4,%5,%6,%7}, {%8,%9}, {%0,%1,%2,%3};"
        : "+f"(d[0]), "+f"(d[1]), "+f"(d[2]), "+f"(d[3])
        : "r"(a[0]), "r"(a[1]), "r"(a[2]), "r"(a[3]), "r"(b[0]), "r"(b[1]));
}

// ===========================================================================
// GEMM: C[M,N] = A[M,K] * W[N,K]^T + bias[N]    (tf32 mma.sync)
// 128x128 CTA tile, BK=32, 256 threads (8 warps, 2m x 4n), warp tile 64x32.
// Smem fills: 4 rows x 8 quads per warp, element-XOR swizzle -> conflict-free.
// Fragment reads un-swizzle with (tig ^ (g&3)) -> conflict-free.
// ===========================================================================
#define GPAD 36

__global__ __launch_bounds__(256) void mma_gemm_bias(
    const float* __restrict__ A, const float* __restrict__ W,
    const float* __restrict__ bias, float* __restrict__ C,
    int M, int N, int K)
{
    __shared__ uint32_t As[128][GPAD];
    __shared__ uint32_t Bs[128][GPAD];

    const int t    = threadIdx.x;
    const int wid  = t >> 5;
    const int lane = t & 31;
    const int g    = lane >> 2;
    const int tig  = lane & 3;
    const int wm   = (wid & 1) * 64;
    const int wn   = (wid >> 1) * 32;
    const int m0   = blockIdx.y * 128;
    const int n0   = blockIdx.x * 128;

    // Loader mapping: 4 consecutive rows per warp, 8 quad-columns.
    const int lrow = t >> 3;          // 0..31
    const int lc4  = (t & 7) * 4;     // 0,4,...,28
    const int lsw  = lrow & 3;        // row-XOR swizzle key

    const int gsw = g & 3;            // read-side swizzle key (row = ...+g, g+8)

    float acc[4][4][4];
#pragma unroll
    for (int mf = 0; mf < 4; mf++)
#pragma unroll
        for (int nf = 0; nf < 4; nf++)
#pragma unroll
            for (int r = 0; r < 4; r++) acc[mf][nf][r] = 0.0f;

    const int NC = K >> 5;
    for (int kc = 0; kc < NC; kc++) {
        float4 av[4], wv[4];
#pragma unroll
        for (int i = 0; i < 4; i++) {
            av[i] = *(const float4*)(A + (size_t)(m0 + i * 32 + lrow) * K + kc * 32 + lc4);
            wv[i] = *(const float4*)(W + (size_t)(n0 + i * 32 + lrow) * K + kc * 32 + lc4);
        }
        __syncthreads();
#pragma unroll
        for (int i = 0; i < 4; i++) {
            int row = i * 32 + lrow;
            As[row][lc4 + (0 ^ lsw)] = f2tf(av[i].x);
            As[row][lc4 + (1 ^ lsw)] = f2tf(av[i].y);
            As[row][lc4 + (2 ^ lsw)] = f2tf(av[i].z);
            As[row][lc4 + (3 ^ lsw)] = f2tf(av[i].w);
            Bs[row][lc4 + (0 ^ lsw)] = f2tf(wv[i].x);
            Bs[row][lc4 + (1 ^ lsw)] = f2tf(wv[i].y);
            Bs[row][lc4 + (2 ^ lsw)] = f2tf(wv[i].z);
            Bs[row][lc4 + (3 ^ lsw)] = f2tf(wv[i].w);
        }
        __syncthreads();

#pragma unroll
        for (int kk = 0; kk < 4; kk++) {
            const int ca = kk * 8 + (tig ^ gsw);
            uint32_t a[4][4];
#pragma unroll
            for (int mf = 0; mf < 4; mf++) {
                int m = wm + mf * 16;
                a[mf][0] = As[m + g    ][ca];
                a[mf][1] = As[m + g + 8][ca];
                a[mf][2] = As[m + g    ][ca + 4];
                a[mf][3] = As[m + g + 8][ca + 4];
            }
#pragma unroll
            for (int nf = 0; nf < 4; nf++) {
                uint32_t b[2];
                int n = wn + nf * 8;
                b[0] = Bs[n + g][ca];
                b[1] = Bs[n + g][ca + 4];
#pragma unroll
                for (int mf = 0; mf < 4; mf++)
                    mma8(acc[mf][nf], a[mf], b);
            }
        }
    }

    // Epilogue with bias. c0,c1 = row g cols (2tig,2tig+1); c2,c3 = row g+8.
#pragma unroll
    for (int mf = 0; mf < 4; mf++) {
#pragma unroll
        for (int nf = 0; nf < 4; nf++) {
            int row = m0 + wm + mf * 16 + g;
            int col = n0 + wn + nf * 8 + 2 * tig;
            float2 bv = *(const float2*)(bias + col);
            float2 o0 = make_float2(acc[mf][nf][0] + bv.x, acc[mf][nf][1] + bv.y);
            float2 o1 = make_float2(acc[mf][nf][2] + bv.x, acc[mf][nf][3] + bv.y);
            *(float2*)(C + (size_t)row * N + col)       = o0;
            *(float2*)(C + (size_t)(row + 8) * N + col) = o1;
        }
    }
}

// ===========================================================================
// Flash attention, tf32 mma.sync. CTA = 128 query rows x 64-key tiles.
// 128 threads = 4 warps; warp owns 32 q rows (2 m-frags) x all 64 keys.
// Q/K swizzled smem (conflict-free fills+reads); V row-major (~2-way B reads);
// P staged per-warp in smem (warp-local, __syncwarp only).
// ===========================================================================
#define APAD 68
#define ATTN_SMEM ((128 + 64 + 64 + 128) * APAD * (int)sizeof(uint32_t))

__global__ __launch_bounds__(128) void flash_attn_tf32(
    const float* __restrict__ qkv,   // [B,S,3E]
    float* __restrict__ ctx)         // [B,S,E]
{
    extern __shared__ uint32_t smu[];
    uint32_t (*Qs)[APAD] = (uint32_t(*)[APAD])smu;   // [128 qrow][64 d]  swizzled
    uint32_t (*Ks)[APAD] = Qs + 128;                 // [64 key][64 d]    swizzled
    uint32_t (*Vs)[APAD] = Ks + 64;                  // [64 key][64 d]    swizzled
    uint32_t (*Ps)[APAD] = Vs + 64;                  // [128 qrow][64 key] plain

    const int t    = threadIdx.x;
    const int wid  = t >> 5;
    const int lane = t & 31;
    const int g    = lane >> 2;
    const int tig  = lane & 3;
    const int wq   = wid * 32;        // warp's q-row base
    const int gsw  = g & 3;

    const int q0 = blockIdx.x * 128;
    const int bh = blockIdx.y;
    const int b  = bh >> 4;
    const int h  = bh & 15;

    const size_t rowstride = 3 * CE;
    const float* qbase = qkv + (size_t)b * CS * rowstride + h * CHD;
    const float* kbase = qbase + CE;
    const float* vbase = qbase + 2 * CE;

    // Loader mapping: 4 consecutive rows per warp, 8 quad-cols, XOR swizzle.
    const int lr8 = t >> 3;           // 0..15
    const int lc8 = (t & 7) * 4;      // 0..28
    const int lsw = lr8 & 3;

    // ---- Load Q tile [128 x 64], pre-scaled by 0.125, swizzled ----
#pragma unroll
    for (int it = 0; it < 16; it++) {
        int row = (it >> 1) * 16 + lr8;
        int c4  = lc8 + (it & 1) * 32;
        float4 v = *(const float4*)(qbase + (size_t)(q0 + row) * rowstride + c4);
        Qs[row][c4 + (0 ^ lsw)] = f2tf(v.x * 0.125f);
        Qs[row][c4 + (1 ^ lsw)] = f2tf(v.y * 0.125f);
        Qs[row][c4 + (2 ^ lsw)] = f2tf(v.z * 0.125f);
        Qs[row][c4 + (3 ^ lsw)] = f2tf(v.w * 0.125f);
    }

    float m_i[2][2], l_i[2][2];
    float o[2][8][4];
#pragma unroll
    for (int mf = 0; mf < 2; mf++) {
        m_i[mf][0] = m_i[mf][1] = -3.0e38f;
        l_i[mf][0] = l_i[mf][1] = 0.0f;
#pragma unroll
        for (int nf = 0; nf < 8; nf++)
#pragma unroll
            for (int r = 0; r < 4; r++) o[mf][nf][r] = 0.0f;
    }

    for (int kt = 0; kt < CS / 64; kt++) {
        const int k0 = kt * 64;
        __syncthreads();   // prev tile's K/V reads done (covers Q stores on kt=0)

        // ---- Load K and V tiles [64 x 64] ----
#pragma unroll
        for (int it = 0; it < 8; it++) {
            int row = (it >> 1) * 16 + lr8;
            int c4  = lc8 + (it & 1) * 32;
            float4 kv = *(const float4*)(kbase + (size_t)(k0 + row) * rowstride + c4);
            float4 vv = *(const float4*)(vbase + (size_t)(k0 + row) * rowstride + c4);
            Ks[row][c4 + (0 ^ lsw)] = f2tf(kv.x);
            Ks[row][c4 + (1 ^ lsw)] = f2tf(kv.y);
            Ks[row][c4 + (2 ^ lsw)] = f2tf(kv.z);
            Ks[row][c4 + (3 ^ lsw)] = f2tf(kv.w);
            Vs[row][c4 + (0 ^ lsw)] = f2tf(vv.x);
            Vs[row][c4 + (1 ^ lsw)] = f2tf(vv.y);
            Vs[row][c4 + (2 ^ lsw)] = f2tf(vv.z);
            Vs[row][c4 + (3 ^ lsw)] = f2tf(vv.w);
        }
        __syncthreads();

        // ---- S = Q K^T  (32q x 64k per warp) ----
        float s[2][8][4];
#pragma unroll
        for (int mf = 0; mf < 2; mf++)
#pragma unroll
            for (int nf = 0; nf < 8; nf++)
#pragma unroll
                for (int r = 0; r < 4; r++) s[mf][nf][r] = 0.0f;

#pragma unroll
        for (int kk = 0; kk < 8; kk++) {
            const int ca = kk * 8 + (tig ^ gsw);
            uint32_t a[2][4];
#pragma unroll
            for (int mf = 0; mf < 2; mf++) {
                int m = wq + mf * 16;
                a[mf][0] = Qs[m + g    ][ca];
                a[mf][1] = Qs[m + g + 8][ca];
                a[mf][2] = Qs[m + g    ][ca + 4];
                a[mf][3] = Qs[m + g + 8][ca + 4];
            }
#pragma unroll
            for (int nf = 0; nf < 8; nf++) {
                uint32_t bb[2];
                bb[0] = Ks[nf * 8 + g][ca];
                bb[1] = Ks[nf * 8 + g][ca + 4];
                mma8(s[0][nf], a[0], bb);
                mma8(s[1][nf], a[1], bb);
            }
        }

        // ---- online softmax (per mf: rows g and g+8; quad shfl-reduce) ----
#pragma unroll
        for (int mf = 0; mf < 2; mf++) {
            float mx0 = -3.0e38f, mx1 = -3.0e38f;
#pragma unroll
            for (int nf = 0; nf < 8; nf++) {
                mx0 = fmaxf(mx0, fmaxf(s[mf][nf][0], s[mf][nf][1]));
                mx1 = fmaxf(mx1, fmaxf(s[mf][nf][2], s[mf][nf][3]));
            }
            mx0 = fmaxf(mx0, __shfl_xor_sync(0xffffffffu, mx0, 1));
            mx0 = fmaxf(mx0, __shfl_xor_sync(0xffffffffu, mx0, 2));
            mx1 = fmaxf(mx1, __shfl_xor_sync(0xffffffffu, mx1, 1));
            mx1 = fmaxf(mx1, __shfl_xor_sync(0xffffffffu, mx1, 2));

            float mn0 = fmaxf(m_i[mf][0], mx0);
            float mn1 = fmaxf(m_i[mf][1], mx1);
            float corr0 = __expf(m_i[mf][0] - mn0);
            float corr1 = __expf(m_i[mf][1] - mn1);
            float sum0 = 0.0f, sum1 = 0.0f;
#pragma unroll
            for (int nf = 0; nf < 8; nf++) {
                s[mf][nf][0] = __expf(s[mf][nf][0] - mn0);
                s[mf][nf][1] = __expf(s[mf][nf][1] - mn0);
                s[mf][nf][2] = __expf(s[mf][nf][2] - mn1);
                s[mf][nf][3] = __expf(s[mf][nf][3] - mn1);
                sum0 += s[mf][nf][0] + s[mf][nf][1];
                sum1 += s[mf][nf][2] + s[mf][nf][3];
            }
            sum0 += __shfl_xor_sync(0xffffffffu, sum0, 1);
            sum0 += __shfl_xor_sync(0xffffffffu, sum0, 2);
            sum1 += __shfl_xor_sync(0xffffffffu, sum1, 1);
            sum1 += __shfl_xor_sync(0xffffffffu, sum1, 2);

            l_i[mf][0] = l_i[mf][0] * corr0 + sum0;
            l_i[mf][1] = l_i[mf][1] * corr1 + sum1;
            m_i[mf][0] = mn0;
            m_i[mf][1] = mn1;
#pragma unroll
            for (int nf = 0; nf < 8; nf++) {
                o[mf][nf][0] *= corr0; o[mf][nf][1] *= corr0;
                o[mf][nf][2] *= corr1; o[mf][nf][3] *= corr1;
            }

            // Store P (tf32) to this warp's rows of Ps (plain layout).
#pragma unroll
            for (int nf = 0; nf < 8; nf++) {
                uint2 p0 = make_uint2(f2tf(s[mf][nf][0]), f2tf(s[mf][nf][1]));
                uint2 p1 = make_uint2(f2tf(s[mf][nf][2]), f2tf(s[mf][nf][3]));
                *(uint2*)&Ps[wq + mf * 16 + g    ][nf * 8 + 2 * tig] = p0;
                *(uint2*)&Ps[wq + mf * 16 + g + 8][nf * 8 + 2 * tig] = p1;
            }
        }
        __syncwarp();   // warp reads only its own 32 rows of Ps

        // ---- O += P V  (A from Ps plain; B from row-major swizzled Vs) ----
#pragma unroll
        for (int kk = 0; kk < 8; kk++) {
            uint32_t a[2][4];
#pragma unroll
            for (int mf = 0; mf < 2; mf++) {
                int m = wq + mf * 16;
                a[mf][0] = Ps[m + g    ][kk * 8 + tig];
                a[mf][1] = Ps[m + g + 8][kk * 8 + tig];
                a[mf][2] = Ps[m + g    ][kk * 8 + tig + 4];
                a[mf][3] = Ps[m + g + 8][kk * 8 + tig + 4];
            }
#pragma unroll
            for (int nf = 0; nf < 8; nf++) {
                // V[key][d]: key = kk*8+tig (+4), d = nf*8+g; swizzle key uses (key&3)=tig
                const int pvcol = nf * 8 + (g & 4) + ((g & 3) ^ tig);
                uint32_t bb[2];
                bb[0] = Vs[kk * 8 + tig    ][pvcol];
                bb[1] = Vs[kk * 8 + tig + 4][pvcol];
                mma8(o[0][nf], a[0], bb);
                mma8(o[1][nf], a[1], bb);
            }
        }
    }

    // ---- Normalize + write ctx[b, q0+row, h*64 + col] ----
#pragma unroll
    for (int mf = 0; mf < 2; mf++) {
        float inv0 = 1.0f / l_i[mf][0];
        float inv1 = 1.0f / l_i[mf][1];
#pragma unroll
        for (int nf = 0; nf < 8; nf++) {
            int row = q0 + wq + mf * 16 + g;
            int col = h * CHD + nf * 8 + 2 * tig;
            float2 r0 = make_float2(o[mf][nf][0] * inv0, o[mf][nf][1] * inv0);
            float2 r1 = make_float2(o[mf][nf][2] * inv1, o[mf][nf][3] * inv1);
            *(float2*)(ctx + ((size_t)b * CS + row)     * CE + col) = r0;
            *(float2*)(ctx + ((size_t)b * CS + row + 8) * CE + col) = r1;
        }
    }
}

// ---------------------------------------------------------------------------
extern "C" void kernel_launch(void* const* d_in, const int* in_sizes, int n_in,
                              void* d_out, int out_size)
{
    const float* query = (const float*)d_in[0];
    const float* qkv_w = (const float*)d_in[3];
    const float* qkv_b = (const float*)d_in[4];
    const float* out_w = (const float*)d_in[5];
    const float* out_b = (const float*)d_in[6];
    float* out = (float*)d_out;

    float *qkv_buf = nullptr, *ctx_buf = nullptr;
    cudaGetSymbolAddress((void**)&qkv_buf, g_qkv);
    cudaGetSymbolAddress((void**)&ctx_buf, g_ctx);

    cudaFuncSetAttribute(flash_attn_tf32,
                         cudaFuncAttributeMaxDynamicSharedMemorySize, ATTN_SMEM);

    // 1) QKV projection: [4096,1024] x [3072,1024]^T -> [4096,3072]
    mma_gemm_bias<<<dim3(3 * CE / 128, CB * CS / 128), 256>>>(
        query, qkv_w, qkv_b, qkv_buf, CB * CS, 3 * CE, CE);

    // 2) Attention: 16 q-tiles x (B*H)=32
    flash_attn_tf32<<<dim3(CS / 128, CB * CH), 128, ATTN_SMEM>>>(qkv_buf, ctx_buf);

    // 3) Output projection: [4096,1024] x [1024,1024]^T -> [4096,1024]
    mma_gemm_bias<<<dim3(CE / 128, CB * CS / 128), 256>>>(
        ctx_buf, out_w, out_b, out, CB * CS, CE, CE);
}

// round 6
// speedup vs baseline: 3.8080x; 1.2569x over previous
#include <cuda_runtime.h>
#include <cuda_fp16.h>
#include <cstdint>
#include <math.h>

// Problem constants
#define CB  2
#define CS  2048
#define CE  1024
#define CH  16
#define CHD 64

// Scratch (no cudaMalloc allowed)
__device__ float g_qkv[(size_t)CB * CS * 3 * CE];   // [B,S,3E]
__device__ float g_ctx[(size_t)CB * CS * CE];       // [B,S,E]

// ---------------------------------------------------------------------------
// helpers (plain sm_80-era PTX; no 'a'-suffix features)
// ---------------------------------------------------------------------------
__device__ __forceinline__ uint32_t smem_u32(const void* p) {
    uint32_t a;
    asm("{ .reg .u64 t; cvta.to.shared.u64 t, %1; cvt.u32.u64 %0, t; }"
        : "=r"(a) : "l"(p));
    return a;
}

__device__ __forceinline__ uint32_t f2tf(float x) {
    uint32_t r;
    asm("cvt.rna.tf32.f32 %0, %1;" : "=r"(r) : "f"(x));
    return r;
}

__device__ __forceinline__ uint32_t f2h2(float lo, float hi) {
    __half2 v = __floats2half2_rn(lo, hi);
    return *(uint32_t*)&v;
}

// tf32: D += A(16x8) * B(8x8)
__device__ __forceinline__ void mma8(float* d, const uint32_t* a, const uint32_t* b) {
    asm volatile(
        "mma.sync.aligned.m16n8k8.row.col.f32.tf32.tf32.f32 "
        "{%0,%1,%2,%3}, {%4,%5,%6,%7}, {%8,%9}, {%0,%1,%2,%3};"
        : "+f"(d[0]), "+f"(d[1]), "+f"(d[2]), "+f"(d[3])
        : "r"(a[0]), "r"(a[1]), "r"(a[2]), "r"(a[3]), "r"(b[0]), "r"(b[1]));
}

// fp16: D += A(16x16) * B(16x8), fp32 accum
__device__ __forceinline__ void mma16(float* d, const uint32_t* a, const uint32_t* b) {
    asm volatile(
        "mma.sync.aligned.m16n8k16.row.col.f32.f16.f16.f32 "
        "{%0,%1,%2,%3}, {%4,%5,%6,%7}, {%8,%9}, {%0,%1,%2,%3};"
        : "+f"(d[0]), "+f"(d[1]), "+f"(d[2]), "+f"(d[3])
        : "r"(a[0]), "r"(a[1]), "r"(a[2]), "r"(a[3]), "r"(b[0]), "r"(b[1]));
}

__device__ __forceinline__ void ldsm_x4(uint32_t* r, uint32_t addr) {
    asm volatile("ldmatrix.sync.aligned.m8n8.x4.shared.b16 {%0,%1,%2,%3}, [%4];"
        : "=r"(r[0]), "=r"(r[1]), "=r"(r[2]), "=r"(r[3]) : "r"(addr));
}
__device__ __forceinline__ void ldsm_x4_t(uint32_t* r, uint32_t addr) {
    asm volatile("ldmatrix.sync.aligned.m8n8.x4.trans.shared.b16 {%0,%1,%2,%3}, [%4];"
        : "=r"(r[0]), "=r"(r[1]), "=r"(r[2]), "=r"(r[3]) : "r"(addr));
}

__device__ __forceinline__ void cp16(uint32_t saddr, const void* g) {
    asm volatile("cp.async.cg.shared.global [%0], [%1], 16;"
        :: "r"(saddr), "l"(g) : "memory");
}

// ===========================================================================
// GEMM: C[M,N] = A[M,K] * W[N,K]^T + bias[N]   (tf32 mma.sync, cp.async x3)
// 128x128 CTA tile, BK=32, 256 threads (8 warps, 2m x 4n), warp tile 64x32.
// Raw fp32 staged in smem (stride 36 -> conflict-free frag reads), cvt on read.
// ===========================================================================
#define GSTG 3
#define GSTR 36
#define GEMM_SMEM (GSTG * 2 * 128 * GSTR * 4)   // 110592 B

__global__ __launch_bounds__(256, 2) void mma_gemm_bias(
    const float* __restrict__ A, const float* __restrict__ W,
    const float* __restrict__ bias, float* __restrict__ C,
    int M, int N, int K)
{
    extern __shared__ float gsm[];
    float (*As)[128][GSTR] = (float(*)[128][GSTR])gsm;
    float (*Bs)[128][GSTR] = As + GSTG;

    const int t    = threadIdx.x;
    const int wid  = t >> 5;
    const int lane = t & 31;
    const int g    = lane >> 2;
    const int tig  = lane & 3;
    const int wm   = (wid & 1) * 64;
    const int wn   = (wid >> 1) * 32;
    const int m0   = blockIdx.y * 128;
    const int n0   = blockIdx.x * 128;

    const uint32_t sa = smem_u32(gsm);
    const uint32_t sb = sa + GSTG * 128 * GSTR * 4;

    float acc[4][4][4];
#pragma unroll
    for (int mf = 0; mf < 4; mf++)
#pragma unroll
        for (int nf = 0; nf < 4; nf++)
#pragma unroll
            for (int r = 0; r < 4; r++) acc[mf][nf][r] = 0.0f;

    const int NC = K >> 5;

    // cp mapping: idx = t + i*256 -> row = idx>>3 (0..127), chunk = idx&7 (16B)
    auto issue = [&](int st, int kc) {
#pragma unroll
        for (int i = 0; i < 4; i++) {
            int idx = t + i * 256;
            int row = idx >> 3;
            int ch  = idx & 7;
            uint32_t off = (uint32_t)((st * 128 + row) * GSTR + ch * 4) * 4;
            cp16(sa + off, A + (size_t)(m0 + row) * K + kc * 32 + ch * 4);
            cp16(sb + off, W + (size_t)(n0 + row) * K + kc * 32 + ch * 4);
        }
        asm volatile("cp.async.commit_group;" ::: "memory");
    };

    issue(0, 0);
    issue(1, 1);

    for (int kc = 0; kc < NC; kc++) {
        if (kc < NC - 1)
            asm volatile("cp.async.wait_group 1;" ::: "memory");
        else
            asm volatile("cp.async.wait_group 0;" ::: "memory");
        __syncthreads();
        if (kc + 2 < NC) issue((kc + 2) % GSTG, kc + 2);

        const float (*Ac)[GSTR] = As[kc % GSTG];
        const float (*Bc)[GSTR] = Bs[kc % GSTG];

#pragma unroll
        for (int kk = 0; kk < 4; kk++) {
            const int ca = kk * 8 + tig;
            uint32_t a[4][4];
#pragma unroll
            for (int mf = 0; mf < 4; mf++) {
                int m = wm + mf * 16;
                a[mf][0] = f2tf(Ac[m + g    ][ca]);
                a[mf][1] = f2tf(Ac[m + g + 8][ca]);
                a[mf][2] = f2tf(Ac[m + g    ][ca + 4]);
                a[mf][3] = f2tf(Ac[m + g + 8][ca + 4]);
            }
#pragma unroll
            for (int nf = 0; nf < 4; nf++) {
                uint32_t b[2];
                int n = wn + nf * 8;
                b[0] = f2tf(Bc[n + g][ca]);
                b[1] = f2tf(Bc[n + g][ca + 4]);
#pragma unroll
                for (int mf = 0; mf < 4; mf++)
                    mma8(acc[mf][nf], a[mf], b);
            }
        }
        __syncthreads();
    }

    // Epilogue with bias. c0,c1 = row g cols (2tig,2tig+1); c2,c3 = row g+8.
#pragma unroll
    for (int mf = 0; mf < 4; mf++) {
#pragma unroll
        for (int nf = 0; nf < 4; nf++) {
            int row = m0 + wm + mf * 16 + g;
            int col = n0 + wn + nf * 8 + 2 * tig;
            float2 bv = *(const float2*)(bias + col);
            float2 o0 = make_float2(acc[mf][nf][0] + bv.x, acc[mf][nf][1] + bv.y);
            float2 o1 = make_float2(acc[mf][nf][2] + bv.x, acc[mf][nf][3] + bv.y);
            *(float2*)(C + (size_t)row * N + col)       = o0;
            *(float2*)(C + (size_t)(row + 8) * N + col) = o1;
        }
    }
}

// ===========================================================================
// Flash attention, fp16 mma.sync (m16n8k16, fp32 accum).
// CTA = 128 q x 64-key tiles, 128 threads = 4 warps x 32 q rows.
// All tiles fp16, row stride 72 halves (144B) -> ldmatrix phases conflict-free.
// V row-major + ldmatrix.trans for PV B-frags (no transpose store).
// ===========================================================================
#define AQW 36   // uint32 words per smem row (72 halves)
#define ATTN_SMEM ((128 + 64 + 64 + 128) * AQW * 4)

__global__ __launch_bounds__(128) void flash_attn_f16(
    const float* __restrict__ qkv,   // [B,S,3E]
    float* __restrict__ ctx)         // [B,S,E]
{
    extern __shared__ uint32_t smu[];
    uint32_t (*Qh)[AQW] = (uint32_t(*)[AQW])smu;   // [128 q][64 d]   fp16
    uint32_t (*Kh)[AQW] = Qh + 128;                // [64 key][64 d]  fp16
    uint32_t (*Vh)[AQW] = Kh + 64;                 // [64 key][64 d]  fp16
    uint32_t (*Ph)[AQW] = Vh + 64;                 // [128 q][64 key] fp16

    const int t    = threadIdx.x;
    const int wid  = t >> 5;
    const int lane = t & 31;
    const int g    = lane >> 2;
    const int tig  = lane & 3;
    const int wq   = wid * 32;

    const int q0 = blockIdx.x * 128;
    const int bh = blockIdx.y;
    const int b  = bh >> 4;
    const int h  = bh & 15;

    const size_t rowstride = 3 * CE;
    const float* qbase = qkv + (size_t)b * CS * rowstride + h * CHD;
    const float* kbase = qbase + CE;
    const float* vbase = qbase + 2 * CE;

    const uint32_t qsm = smem_u32(smu);
    const uint32_t ksm = qsm + 128 * AQW * 4;
    const uint32_t vsm = ksm + 64 * AQW * 4;
    const uint32_t psm = vsm + 64 * AQW * 4;

    // ldmatrix per-lane address components
    const int seg = lane >> 3;            // 0..3
    const int r8  = lane & 7;
    const int arow = r8 + (seg & 1) * 8;  // A-pattern (Q/P) and V-trans pattern
    const int ach  = seg >> 1;
    const int krow = r8 + (seg >> 1) * 8; // K B-pattern
    const int kch  = seg & 1;

    // Loader mapping: 16 rows x 8 chunks (8 floats -> 8 halves = 16B)
    const int lrow = t >> 3;   // 0..15
    const int lch  = t & 7;    // 0..7

    // ---- Load Q tile [128 x 64] fp16, pre-scaled by 0.125 ----
#pragma unroll
    for (int st = 0; st < 8; st++) {
        int row = st * 16 + lrow;
        const float* p = qbase + (size_t)(q0 + row) * rowstride + lch * 8;
        float4 v0 = *(const float4*)p;
        float4 v1 = *(const float4*)(p + 4);
        uint4 pk;
        pk.x = f2h2(v0.x * 0.125f, v0.y * 0.125f);
        pk.y = f2h2(v0.z * 0.125f, v0.w * 0.125f);
        pk.z = f2h2(v1.x * 0.125f, v1.y * 0.125f);
        pk.w = f2h2(v1.z * 0.125f, v1.w * 0.125f);
        *(uint4*)&Qh[row][lch * 4] = pk;
    }

    float m_i[2][2], l_i[2][2];
    float o[2][8][4];
#pragma unroll
    for (int mf = 0; mf < 2; mf++) {
        m_i[mf][0] = m_i[mf][1] = -3.0e38f;
        l_i[mf][0] = l_i[mf][1] = 0.0f;
#pragma unroll
        for (int nf = 0; nf < 8; nf++)
#pragma unroll
            for (int r = 0; r < 4; r++) o[mf][nf][r] = 0.0f;
    }

    for (int kt = 0; kt < CS / 64; kt++) {
        const int k0 = kt * 64;
        __syncthreads();   // prev tile's K/V reads done (covers Q stores on kt=0)

        // ---- Load K and V tiles [64 x 64] fp16 ----
#pragma unroll
        for (int st = 0; st < 4; st++) {
            int row = st * 16 + lrow;
            const float* kp = kbase + (size_t)(k0 + row) * rowstride + lch * 8;
            const float* vp = vbase + (size_t)(k0 + row) * rowstride + lch * 8;
            float4 k0v = *(const float4*)kp;
            float4 k1v = *(const float4*)(kp + 4);
            float4 v0v = *(const float4*)vp;
            float4 v1v = *(const float4*)(vp + 4);
            uint4 pk, pv;
            pk.x = f2h2(k0v.x, k0v.y); pk.y = f2h2(k0v.z, k0v.w);
            pk.z = f2h2(k1v.x, k1v.y); pk.w = f2h2(k1v.z, k1v.w);
            pv.x = f2h2(v0v.x, v0v.y); pv.y = f2h2(v0v.z, v0v.w);
            pv.z = f2h2(v1v.x, v1v.y); pv.w = f2h2(v1v.z, v1v.w);
            *(uint4*)&Kh[row][lch * 4] = pk;
            *(uint4*)&Vh[row][lch * 4] = pv;
        }
        __syncthreads();

        // ---- S = Q K^T  (32q x 64k per warp), 4 k16-steps ----
        float s[2][8][4];
#pragma unroll
        for (int mf = 0; mf < 2; mf++)
#pragma unroll
            for (int nf = 0; nf < 8; nf++)
#pragma unroll
                for (int r = 0; r < 4; r++) s[mf][nf][r] = 0.0f;

#pragma unroll
        for (int kk = 0; kk < 4; kk++) {
            uint32_t aq[2][4];
#pragma unroll
            for (int mf = 0; mf < 2; mf++)
                ldsm_x4(aq[mf], qsm + ((wq + mf * 16 + arow) * AQW + (kk * 2 + ach) * 4) * 4);
#pragma unroll
            for (int nfp = 0; nfp < 4; nfp++) {
                uint32_t kb[4];
                ldsm_x4(kb, ksm + ((nfp * 16 + krow) * AQW + (kk * 2 + kch) * 4) * 4);
                mma16(s[0][nfp * 2    ], aq[0], kb);
                mma16(s[0][nfp * 2 + 1], aq[0], kb + 2);
                mma16(s[1][nfp * 2    ], aq[1], kb);
                mma16(s[1][nfp * 2 + 1], aq[1], kb + 2);
            }
        }

        // ---- online softmax (rows g and g+8 per mf; quad shfl-reduce) ----
#pragma unroll
        for (int mf = 0; mf < 2; mf++) {
            float mx0 = -3.0e38f, mx1 = -3.0e38f;
#pragma unroll
            for (int nf = 0; nf < 8; nf++) {
                mx0 = fmaxf(mx0, fmaxf(s[mf][nf][0], s[mf][nf][1]));
                mx1 = fmaxf(mx1, fmaxf(s[mf][nf][2], s[mf][nf][3]));
            }
            mx0 = fmaxf(mx0, __shfl_xor_sync(0xffffffffu, mx0, 1));
            mx0 = fmaxf(mx0, __shfl_xor_sync(0xffffffffu, mx0, 2));
            mx1 = fmaxf(mx1, __shfl_xor_sync(0xffffffffu, mx1, 1));
            mx1 = fmaxf(mx1, __shfl_xor_sync(0xffffffffu, mx1, 2));

            float mn0 = fmaxf(m_i[mf][0], mx0);
            float mn1 = fmaxf(m_i[mf][1], mx1);
            float corr0 = __expf(m_i[mf][0] - mn0);
            float corr1 = __expf(m_i[mf][1] - mn1);
            float sum0 = 0.0f, sum1 = 0.0f;
#pragma unroll
            for (int nf = 0; nf < 8; nf++) {
                s[mf][nf][0] = __expf(s[mf][nf][0] - mn0);
                s[mf][nf][1] = __expf(s[mf][nf][1] - mn0);
                s[mf][nf][2] = __expf(s[mf][nf][2] - mn1);
                s[mf][nf][3] = __expf(s[mf][nf][3] - mn1);
                sum0 += s[mf][nf][0] + s[mf][nf][1];
                sum1 += s[mf][nf][2] + s[mf][nf][3];
            }
            sum0 += __shfl_xor_sync(0xffffffffu, sum0, 1);
            sum0 += __shfl_xor_sync(0xffffffffu, sum0, 2);
            sum1 += __shfl_xor_sync(0xffffffffu, sum1, 1);
            sum1 += __shfl_xor_sync(0xffffffffu, sum1, 2);

            l_i[mf][0] = l_i[mf][0] * corr0 + sum0;
            l_i[mf][1] = l_i[mf][1] * corr1 + sum1;
            m_i[mf][0] = mn0;
            m_i[mf][1] = mn1;
#pragma unroll
            for (int nf = 0; nf < 8; nf++) {
                o[mf][nf][0] *= corr0; o[mf][nf][1] *= corr0;
                o[mf][nf][2] *= corr1; o[mf][nf][3] *= corr1;
            }

            // Store P fp16 (half2 per store; conflict-free banks)
#pragma unroll
            for (int nf = 0; nf < 8; nf++) {
                Ph[wq + mf * 16 + g    ][nf * 4 + tig] = f2h2(s[mf][nf][0], s[mf][nf][1]);
                Ph[wq + mf * 16 + g + 8][nf * 4 + tig] = f2h2(s[mf][nf][2], s[mf][nf][3]);
            }
        }
        __syncwarp();   // warp reads only its own 32 rows of Ph

        // ---- O += P V  (A from Ph; B via ldmatrix.trans on row-major Vh) ----
#pragma unroll
        for (int kk = 0; kk < 4; kk++) {
            uint32_t ap[2][4];
#pragma unroll
            for (int mf = 0; mf < 2; mf++)
                ldsm_x4(ap[mf], psm + ((wq + mf * 16 + arow) * AQW + (kk * 2 + ach) * 4) * 4);
#pragma unroll
            for (int nfp = 0; nfp < 4; nfp++) {
                uint32_t vb[4];
                ldsm_x4_t(vb, vsm + ((kk * 16 + arow) * AQW + (nfp * 2 + ach) * 4) * 4);
                mma16(o[0][nfp * 2    ], ap[0], vb);
                mma16(o[0][nfp * 2 + 1], ap[0], vb + 2);
                mma16(o[1][nfp * 2    ], ap[1], vb);
                mma16(o[1][nfp * 2 + 1], ap[1], vb + 2);
            }
        }
    }

    // ---- Normalize + write ctx[b, q0+row, h*64 + col] ----
#pragma unroll
    for (int mf = 0; mf < 2; mf++) {
        float inv0 = 1.0f / l_i[mf][0];
        float inv1 = 1.0f / l_i[mf][1];
#pragma unroll
        for (int nf = 0; nf < 8; nf++) {
            int row = q0 + wq + mf * 16 + g;
            int col = h * CHD + nf * 8 + 2 * tig;
            float2 r0 = make_float2(o[mf][nf][0] * inv0, o[mf][nf][1] * inv0);
            float2 r1 = make_float2(o[mf][nf][2] * inv1, o[mf][nf][3] * inv1);
            *(float2*)(ctx + ((size_t)b * CS + row)     * CE + col) = r0;
            *(float2*)(ctx + ((size_t)b * CS + row + 8) * CE + col) = r1;
        }
    }
}

// ---------------------------------------------------------------------------
extern "C" void kernel_launch(void* const* d_in, const int* in_sizes, int n_in,
                              void* d_out, int out_size)
{
    const float* query = (const float*)d_in[0];
    const float* qkv_w = (const float*)d_in[3];
    const float* qkv_b = (const float*)d_in[4];
    const float* out_w = (const float*)d_in[5];
    const float* out_b = (const float*)d_in[6];
    float* out = (float*)d_out;

    float *qkv_buf = nullptr, *ctx_buf = nullptr;
    cudaGetSymbolAddress((void**)&qkv_buf, g_qkv);
    cudaGetSymbolAddress((void**)&ctx_buf, g_ctx);

    cudaFuncSetAttribute(flash_attn_f16,
                         cudaFuncAttributeMaxDynamicSharedMemorySize, ATTN_SMEM);
    cudaFuncSetAttribute(mma_gemm_bias,
                         cudaFuncAttributeMaxDynamicSharedMemorySize, GEMM_SMEM);

    // 1) QKV projection: [4096,1024] x [3072,1024]^T -> [4096,3072]
    mma_gemm_bias<<<dim3(3 * CE / 128, CB * CS / 128), 256, GEMM_SMEM>>>(
        query, qkv_w, qkv_b, qkv_buf, CB * CS, 3 * CE, CE);

    // 2) Attention: 16 q-tiles x (B*H)=32
    flash_attn_f16<<<dim3(CS / 128, CB * CH), 128, ATTN_SMEM>>>(qkv_buf, ctx_buf);

    // 3) Output projection: [4096,1024] x [1024,1024]^T -> [4096,1024]
    mma_gemm_bias<<<dim3(CE / 128, CB * CS / 128), 256, GEMM_SMEM>>>(
        ctx_buf, out_w, out_b, out, CB * CS, CE, CE);
}

// round 9
// speedup vs baseline: 3.8957x; 1.0230x over previous
#include <cuda_runtime.h>
#include <cuda_fp16.h>
#include <cstdint>
#include <math.h>

// Problem constants
#define CB  2
#define CS  2048
#define CE  1024
#define CH  16
#define CHD 64

// Scratch (no cudaMalloc allowed)
__device__ float    g_qkv[(size_t)CB * CS * 3 * CE];  // [B,S,3E] fp32 (QKV out)
__device__ uint32_t g_ctx[(size_t)CB * CS * CE];      // [B,S,E]  tf32 bits
__device__ uint32_t g_qt [(size_t)CB * CS * CE];      // query    tf32 bits
__device__ uint32_t g_wq [(size_t)3 * CE * CE];       // qkv_w    tf32 bits
__device__ uint32_t g_wo [(size_t)CE * CE];           // out_w    tf32 bits

// ---------------------------------------------------------------------------
// helpers (plain sm_80-era PTX; no 'a'-suffix features)
// ---------------------------------------------------------------------------
__device__ __forceinline__ uint32_t smem_u32(const void* p) {
    uint32_t a;
    asm("{ .reg .u64 t; cvta.to.shared.u64 t, %1; cvt.u32.u64 %0, t; }"
        : "=r"(a) : "l"(p));
    return a;
}

__device__ __forceinline__ uint32_t f2tf(float x) {
    uint32_t r;
    asm("cvt.rna.tf32.f32 %0, %1;" : "=r"(r) : "f"(x));
    return r;
}

__device__ __forceinline__ uint32_t f2h2(float lo, float hi) {
    __half2 v = __floats2half2_rn(lo, hi);
    return *(uint32_t*)&v;
}

// tf32: D += A(16x8) * B(8x8)
__device__ __forceinline__ void mma8(float* d, const uint32_t* a, const uint32_t* b) {
    asm volatile(
        "mma.sync.aligned.m16n8k8.row.col.f32.tf32.tf32.f32 "
        "{%0,%1,%2,%3}, {%4,%5,%6,%7}, {%8,%9}, {%0,%1,%2,%3};"
        : "+f"(d[0]), "+f"(d[1]), "+f"(d[2]), "+f"(d[3])
        : "r"(a[0]), "r"(a[1]), "r"(a[2]), "r"(a[3]), "r"(b[0]), "r"(b[1]));
}

// fp16: D += A(16x16) * B(16x8), fp32 accum
__device__ __forceinline__ void mma16(float* d, const uint32_t* a, const uint32_t* b) {
    asm volatile(
        "mma.sync.aligned.m16n8k16.row.col.f32.f16.f16.f32 "
        "{%0,%1,%2,%3}, {%4,%5,%6,%7}, {%8,%9}, {%0,%1,%2,%3};"
        : "+f"(d[0]), "+f"(d[1]), "+f"(d[2]), "+f"(d[3])
        : "r"(a[0]), "r"(a[1]), "r"(a[2]), "r"(a[3]), "r"(b[0]), "r"(b[1]));
}

__device__ __forceinline__ void ldsm_x4(uint32_t* r, uint32_t addr) {
    asm volatile("ldmatrix.sync.aligned.m8n8.x4.shared.b16 {%0,%1,%2,%3}, [%4];"
        : "=r"(r[0]), "=r"(r[1]), "=r"(r[2]), "=r"(r[3]) : "r"(addr));
}
__device__ __forceinline__ void ldsm_x4_t(uint32_t* r, uint32_t addr) {
    asm volatile("ldmatrix.sync.aligned.m8n8.x4.trans.shared.b16 {%0,%1,%2,%3}, [%4];"
        : "=r"(r[0]), "=r"(r[1]), "=r"(r[2]), "=r"(r[3]) : "r"(addr));
}

__device__ __forceinline__ void cp16(uint32_t saddr, const void* g) {
    asm volatile("cp.async.cg.shared.global [%0], [%1], 16;"
        :: "r"(saddr), "l"(g) : "memory");
}

// ---------------------------------------------------------------------------
// Elementwise fp32 -> tf32-bits pre-convert (rna)
// ---------------------------------------------------------------------------
__global__ __launch_bounds__(256) void cvt_tf32(const float* __restrict__ in,
                                                uint32_t* __restrict__ out, int n4)
{
    int i = blockIdx.x * 256 + threadIdx.x;
    if (i < n4) {
        float4 v = *(const float4*)(in + (size_t)i * 4);
        uint4 o = make_uint4(f2tf(v.x), f2tf(v.y), f2tf(v.z), f2tf(v.w));
        *(uint4*)(out + (size_t)i * 4) = o;
    }
}

// ===========================================================================
// GEMM: C[M,N] = A[M,K] * W[N,K]^T + bias[N]
// A and W are PRE-CONVERTED tf32 bits. cp.async 3-stage, ldmatrix fragments.
// 128x128 CTA tile, BK=32, 256 threads (8 warps, 2m x 4n), warp tile 64x32.
// Mainloop per chunk/warp: 24 ldmatrix + 64 mma + 8 cp.async (no cvt, no LDS).
// ===========================================================================
#define GSTG 3
#define GSTR 36
#define GEMM_SMEM (GSTG * 2 * 128 * GSTR * 4)   // 110592 B

__global__ __launch_bounds__(256, 2) void mma_gemm_bias(
    const uint32_t* __restrict__ A, const uint32_t* __restrict__ W,
    const float* __restrict__ bias, float* __restrict__ C,
    int M, int N, int K)
{
    extern __shared__ uint32_t gsm[];

    const int t    = threadIdx.x;
    const int wid  = t >> 5;
    const int lane = t & 31;
    const int g    = lane >> 2;
    const int tig  = lane & 3;
    const int wm   = (wid & 1) * 64;
    const int wn   = (wid >> 1) * 32;
    const int m0   = blockIdx.y * 128;
    const int n0   = blockIdx.x * 128;

    const uint32_t sa = smem_u32(gsm);
    const uint32_t sb = sa + GSTG * 128 * GSTR * 4;

    // ldmatrix lane mapping (same pattern for A and B):
    // rows 0-15 within frag-block, halves 0/16B
    const int lrA   = (lane & 7) + ((lane >> 3) & 1) * 8;  // 0..15
    const int lhalf = (lane >> 4) * 16;                    // 0 or 16 bytes

    float acc[4][4][4];
#pragma unroll
    for (int mf = 0; mf < 4; mf++)
#pragma unroll
        for (int nf = 0; nf < 4; nf++)
#pragma unroll
            for (int r = 0; r < 4; r++) acc[mf][nf][r] = 0.0f;

    const int NC = K >> 5;

    // cp mapping: idx = t + i*256 -> row = idx>>3 (0..127), chunk = idx&7 (16B)
    auto issue = [&](int st, int kc) {
#pragma unroll
        for (int i = 0; i < 4; i++) {
            int idx = t + i * 256;
            int row = idx >> 3;
            int ch  = idx & 7;
            uint32_t off = (uint32_t)((st * 128 + row) * GSTR + ch * 4) * 4;
            cp16(sa + off, A + (size_t)(m0 + row) * K + kc * 32 + ch * 4);
            cp16(sb + off, W + (size_t)(n0 + row) * K + kc * 32 + ch * 4);
        }
        asm volatile("cp.async.commit_group;" ::: "memory");
    };

    issue(0, 0);
    issue(1, 1);

    for (int kc = 0; kc < NC; kc++) {
        if (kc < NC - 1)
            asm volatile("cp.async.wait_group 1;" ::: "memory");
        else
            asm volatile("cp.async.wait_group 0;" ::: "memory");
        __syncthreads();
        if (kc + 2 < NC) issue((kc + 2) % GSTG, kc + 2);

        const int st = kc % GSTG;
        const uint32_t sa0 = sa + ((uint32_t)(st * 128 + wm + lrA) * GSTR) * 4 + lhalf;
        const uint32_t sb0 = sb + ((uint32_t)(st * 128 + wn + lrA) * GSTR) * 4 + lhalf;

#pragma unroll
        for (int kk = 0; kk < 4; kk++) {
            uint32_t a[4][4];
#pragma unroll
            for (int mf = 0; mf < 4; mf++)
                ldsm_x4(a[mf], sa0 + (mf * 16 * GSTR + kk * 8) * 4);
            uint32_t bq[2][4];
            ldsm_x4(bq[0], sb0 + (kk * 8) * 4);                 // nf 0,1
            ldsm_x4(bq[1], sb0 + (16 * GSTR + kk * 8) * 4);     // nf 2,3
#pragma unroll
            for (int p = 0; p < 2; p++) {
                uint32_t b0[2] = { bq[p][0], bq[p][2] };        // nf = 2p
                uint32_t b1[2] = { bq[p][1], bq[p][3] };        // nf = 2p+1
#pragma unroll
                for (int mf = 0; mf < 4; mf++) {
                    mma8(acc[mf][2 * p    ], a[mf], b0);
                    mma8(acc[mf][2 * p + 1], a[mf], b1);
                }
            }
        }
    }

    // Epilogue with bias. c0,c1 = row g cols (2tig,2tig+1); c2,c3 = row g+8.
#pragma unroll
    for (int mf = 0; mf < 4; mf++) {
#pragma unroll
        for (int nf = 0; nf < 4; nf++) {
            int row = m0 + wm + mf * 16 + g;
            int col = n0 + wn + nf * 8 + 2 * tig;
            float2 bv = *(const float2*)(bias + col);
            float2 o0 = make_float2(acc[mf][nf][0] + bv.x, acc[mf][nf][1] + bv.y);
            float2 o1 = make_float2(acc[mf][nf][2] + bv.x, acc[mf][nf][3] + bv.y);
            *(float2*)(C + (size_t)row * N + col)       = o0;
            *(float2*)(C + (size_t)(row + 8) * N + col) = o1;
        }
    }
}

// ===========================================================================
// Flash attention, fp16 mma.sync (m16n8k16, fp32 accum).
// CTA = 128 q x 64-key tiles, 128 threads = 4 warps x 32 q rows.
// All tiles fp16, row stride 72 halves (144B); ldmatrix everywhere.
// Epilogue writes ctx as tf32 bits (feeds out-proj GEMM directly).
// ===========================================================================
#define AQW 36   // uint32 words per smem row (72 halves)
#define ATTN_SMEM ((128 + 64 + 64 + 128) * AQW * 4)

__global__ __launch_bounds__(128) void flash_attn_f16(
    const float* __restrict__ qkv,   // [B,S,3E] fp32
    uint32_t* __restrict__ ctx)      // [B,S,E]  tf32 bits
{
    extern __shared__ uint32_t smu[];
    uint32_t (*Qh)[AQW] = (uint32_t(*)[AQW])smu;   // [128 q][64 d]   fp16
    uint32_t (*Kh)[AQW] = Qh + 128;                // [64 key][64 d]  fp16
    uint32_t (*Vh)[AQW] = Kh + 64;                 // [64 key][64 d]  fp16
    uint32_t (*Ph)[AQW] = Vh + 64;                 // [128 q][64 key] fp16

    const int t    = threadIdx.x;
    const int wid  = t >> 5;
    const int lane = t & 31;
    const int g    = lane >> 2;
    const int tig  = lane & 3;
    const int wq   = wid * 32;

    const int q0 = blockIdx.x * 128;
    const int bh = blockIdx.y;
    const int b  = bh >> 4;
    const int h  = bh & 15;

    const size_t rowstride = 3 * CE;
    const float* qbase = qkv + (size_t)b * CS * rowstride + h * CHD;
    const float* kbase = qbase + CE;
    const float* vbase = qbase + 2 * CE;

    const uint32_t qsm = smem_u32(smu);
    const uint32_t ksm = qsm + 128 * AQW * 4;
    const uint32_t vsm = ksm + 64 * AQW * 4;
    const uint32_t psm = vsm + 64 * AQW * 4;

    // ldmatrix per-lane address components
    const int seg = lane >> 3;            // 0..3
    const int r8  = lane & 7;
    const int arow = r8 + (seg & 1) * 8;  // A-pattern (Q/P) and V-trans pattern
    const int ach  = seg >> 1;
    const int krow = r8 + (seg >> 1) * 8; // K B-pattern
    const int kch  = seg & 1;

    // Loader mapping: 16 rows x 8 chunks (8 floats -> 8 halves = 16B)
    const int lrow = t >> 3;   // 0..15
    const int lch  = t & 7;    // 0..7

    // ---- Load Q tile [128 x 64] fp16, pre-scaled by 0.125 ----
#pragma unroll
    for (int st = 0; st < 8; st++) {
        int row = st * 16 + lrow;
        const float* p = qbase + (size_t)(q0 + row) * rowstride + lch * 8;
        float4 v0 = *(const float4*)p;
        float4 v1 = *(const float4*)(p + 4);
        uint4 pk;
        pk.x = f2h2(v0.x * 0.125f, v0.y * 0.125f);
        pk.y = f2h2(v0.z * 0.125f, v0.w * 0.125f);
        pk.z = f2h2(v1.x * 0.125f, v1.y * 0.125f);
        pk.w = f2h2(v1.z * 0.125f, v1.w * 0.125f);
        *(uint4*)&Qh[row][lch * 4] = pk;
    }

    float m_i[2][2], l_i[2][2];
    float o[2][8][4];
#pragma unroll
    for (int mf = 0; mf < 2; mf++) {
        m_i[mf][0] = m_i[mf][1] = -3.0e38f;
        l_i[mf][0] = l_i[mf][1] = 0.0f;
#pragma unroll
        for (int nf = 0; nf < 8; nf++)
#pragma unroll
            for (int r = 0; r < 4; r++) o[mf][nf][r] = 0.0f;
    }

    for (int kt = 0; kt < CS / 64; kt++) {
        const int k0 = kt * 64;
        __syncthreads();   // prev tile's K/V reads done (covers Q stores on kt=0)

        // ---- Load K and V tiles [64 x 64] fp16 ----
#pragma unroll
        for (int st = 0; st < 4; st++) {
            int row = st * 16 + lrow;
            const float* kp = kbase + (size_t)(k0 + row) * rowstride + lch * 8;
            const float* vp = vbase + (size_t)(k0 + row) * rowstride + lch * 8;
            float4 k0v = *(const float4*)kp;
            float4 k1v = *(const float4*)(kp + 4);
            float4 v0v = *(const float4*)vp;
            float4 v1v = *(const float4*)(vp + 4);
            uint4 pk, pv;
            pk.x = f2h2(k0v.x, k0v.y); pk.y = f2h2(k0v.z, k0v.w);
            pk.z = f2h2(k1v.x, k1v.y); pk.w = f2h2(k1v.z, k1v.w);
            pv.x = f2h2(v0v.x, v0v.y); pv.y = f2h2(v0v.z, v0v.w);
            pv.z = f2h2(v1v.x, v1v.y); pv.w = f2h2(v1v.z, v1v.w);
            *(uint4*)&Kh[row][lch * 4] = pk;
            *(uint4*)&Vh[row][lch * 4] = pv;
        }
        __syncthreads();

        // ---- S = Q K^T  (32q x 64k per warp), 4 k16-steps ----
        float s[2][8][4];
#pragma unroll
        for (int mf = 0; mf < 2; mf++)
#pragma unroll
            for (int nf = 0; nf < 8; nf++)
#pragma unroll
                for (int r = 0; r < 4; r++) s[mf][nf][r] = 0.0f;

#pragma unroll
        for (int kk = 0; kk < 4; kk++) {
            uint32_t aq[2][4];
#pragma unroll
            for (int mf = 0; mf < 2; mf++)
                ldsm_x4(aq[mf], qsm + ((wq + mf * 16 + arow) * AQW + (kk * 2 + ach) * 4) * 4);
#pragma unroll
            for (int nfp = 0; nfp < 4; nfp++) {
                uint32_t kb[4];
                ldsm_x4(kb, ksm + ((nfp * 16 + krow) * AQW + (kk * 2 + kch) * 4) * 4);
                mma16(s[0][nfp * 2    ], aq[0], kb);
                mma16(s[0][nfp * 2 + 1], aq[0], kb + 2);
                mma16(s[1][nfp * 2    ], aq[1], kb);
                mma16(s[1][nfp * 2 + 1], aq[1], kb + 2);
            }
        }

        // ---- online softmax (rows g and g+8 per mf; quad shfl-reduce) ----
#pragma unroll
        for (int mf = 0; mf < 2; mf++) {
            float mx0 = -3.0e38f, mx1 = -3.0e38f;
#pragma unroll
            for (int nf = 0; nf < 8; nf++) {
                mx0 = fmaxf(mx0, fmaxf(s[mf][nf][0], s[mf][nf][1]));
                mx1 = fmaxf(mx1, fmaxf(s[mf][nf][2], s[mf][nf][3]));
            }
            mx0 = fmaxf(mx0, __shfl_xor_sync(0xffffffffu, mx0, 1));
            mx0 = fmaxf(mx0, __shfl_xor_sync(0xffffffffu, mx0, 2));
            mx1 = fmaxf(mx1, __shfl_xor_sync(0xffffffffu, mx1, 1));
            mx1 = fmaxf(mx1, __shfl_xor_sync(0xffffffffu, mx1, 2));

            float mn0 = fmaxf(m_i[mf][0], mx0);
            float mn1 = fmaxf(m_i[mf][1], mx1);
            float corr0 = __expf(m_i[mf][0] - mn0);
            float corr1 = __expf(m_i[mf][1] - mn1);
            float sum0 = 0.0f, sum1 = 0.0f;
#pragma unroll
            for (int nf = 0; nf < 8; nf++) {
                s[mf][nf][0] = __expf(s[mf][nf][0] - mn0);
                s[mf][nf][1] = __expf(s[mf][nf][1] - mn0);
                s[mf][nf][2] = __expf(s[mf][nf][2] - mn1);
                s[mf][nf][3] = __expf(s[mf][nf][3] - mn1);
                sum0 += s[mf][nf][0] + s[mf][nf][1];
                sum1 += s[mf][nf][2] + s[mf][nf][3];
            }
            sum0 += __shfl_xor_sync(0xffffffffu, sum0, 1);
            sum0 += __shfl_xor_sync(0xffffffffu, sum0, 2);
            sum1 += __shfl_xor_sync(0xffffffffu, sum1, 1);
            sum1 += __shfl_xor_sync(0xffffffffu, sum1, 2);

            l_i[mf][0] = l_i[mf][0] * corr0 + sum0;
            l_i[mf][1] = l_i[mf][1] * corr1 + sum1;
            m_i[mf][0] = mn0;
            m_i[mf][1] = mn1;
#pragma unroll
            for (int nf = 0; nf < 8; nf++) {
                o[mf][nf][0] *= corr0; o[mf][nf][1] *= corr0;
                o[mf][nf][2] *= corr1; o[mf][nf][3] *= corr1;
            }

            // Store P fp16 (half2 per store; conflict-free banks)
#pragma unroll
            for (int nf = 0; nf < 8; nf++) {
                Ph[wq + mf * 16 + g    ][nf * 4 + tig] = f2h2(s[mf][nf][0], s[mf][nf][1]);
                Ph[wq + mf * 16 + g + 8][nf * 4 + tig] = f2h2(s[mf][nf][2], s[mf][nf][3]);
            }
        }
        __syncwarp();   // warp reads only its own 32 rows of Ph

        // ---- O += P V  (A from Ph; B via ldmatrix.trans on row-major Vh) ----
#pragma unroll
        for (int kk = 0; kk < 4; kk++) {
            uint32_t ap[2][4];
#pragma unroll
            for (int mf = 0; mf < 2; mf++)
                ldsm_x4(ap[mf], psm + ((wq + mf * 16 + arow) * AQW + (kk * 2 + ach) * 4) * 4);
#pragma unroll
            for (int nfp = 0; nfp < 4; nfp++) {
                uint32_t vb[4];
                ldsm_x4_t(vb, vsm + ((kk * 16 + arow) * AQW + (nfp * 2 + ach) * 4) * 4);
                mma16(o[0][nfp * 2    ], ap[0], vb);
                mma16(o[0][nfp * 2 + 1], ap[0], vb + 2);
                mma16(o[1][nfp * 2    ], ap[1], vb);
                mma16(o[1][nfp * 2 + 1], ap[1], vb + 2);
            }
        }
    }

    // ---- Normalize + write ctx (tf32 bits) [b, q0+row, h*64 + col] ----
#pragma unroll
    for (int mf = 0; mf < 2; mf++) {
        float inv0 = 1.0f / l_i[mf][0];
        float inv1 = 1.0f / l_i[mf][1];
#pragma unroll
        for (int nf = 0; nf < 8; nf++) {
            int row = q0 + wq + mf * 16 + g;
            int col = h * CHD + nf * 8 + 2 * tig;
            uint2 r0 = make_uint2(f2tf(o[mf][nf][0] * inv0), f2tf(o[mf][nf][1] * inv0));
            uint2 r1 = make_uint2(f2tf(o[mf][nf][2] * inv1), f2tf(o[mf][nf][3] * inv1));
            *(uint2*)(ctx + ((size_t)b * CS + row)     * CE + col) = r0;
            *(uint2*)(ctx + ((size_t)b * CS + row + 8) * CE + col) = r1;
        }
    }
}

// ---------------------------------------------------------------------------
extern "C" void kernel_launch(void* const* d_in, const int* in_sizes, int n_in,
                              void* d_out, int out_size)
{
    const float* query = (const float*)d_in[0];
    const float* qkv_w = (const float*)d_in[3];
    const float* qkv_b = (const float*)d_in[4];
    const float* out_w = (const float*)d_in[5];
    const float* out_b = (const float*)d_in[6];
    float* out = (float*)d_out;

    float* qkv_buf = nullptr;
    uint32_t *ctx_buf = nullptr, *qt = nullptr, *wq = nullptr, *wo = nullptr;
    cudaGetSymbolAddress((void**)&qkv_buf, g_qkv);
    cudaGetSymbolAddress((void**)&ctx_buf, g_ctx);
    cudaGetSymbolAddress((void**)&qt, g_qt);
    cudaGetSymbolAddress((void**)&wq, g_wq);
    cudaGetSymbolAddress((void**)&wo, g_wo);

    cudaFuncSetAttribute(flash_attn_f16,
                         cudaFuncAttributeMaxDynamicSharedMemorySize, ATTN_SMEM);
    cudaFuncSetAttribute(mma_gemm_bias,
                         cudaFuncAttributeMaxDynamicSharedMemorySize, GEMM_SMEM);

    // 0) Pre-convert operands to tf32 bits (rna)
    cvt_tf32<<<(CB * CS * CE / 4 + 255) / 256, 256>>>(query, qt, CB * CS * CE / 4);
    cvt_tf32<<<(3 * CE * CE / 4 + 255) / 256, 256>>>(qkv_w, wq, 3 * CE * CE / 4);
    cvt_tf32<<<(CE * CE / 4 + 255) / 256, 256>>>(out_w, wo, CE * CE / 4);

    // 1) QKV projection: [4096,1024] x [3072,1024]^T -> [4096,3072]
    mma_gemm_bias<<<dim3(3 * CE / 128, CB * CS / 128), 256, GEMM_SMEM>>>(
        qt, wq, qkv_b, qkv_buf, CB * CS, 3 * CE, CE);

    // 2) Attention: 16 q-tiles x (B*H)=32 (writes ctx as tf32 bits)
    flash_attn_f16<<<dim3(CS / 128, CB * CH), 128, ATTN_SMEM>>>(qkv_buf, ctx_buf);

    // 3) Output projection: [4096,1024] x [1024,1024]^T -> [4096,1024]
    mma_gemm_bias<<<dim3(CE / 128, CB * CS / 128), 256, GEMM_SMEM>>>(
        ctx_buf, wo, out_b, out, CB * CS, CE, CE);
}

// round 10
// speedup vs baseline: 6.3336x; 1.6258x over previous
#include <cuda_runtime.h>
#include <cuda_fp16.h>
#include <cstdint>
#include <math.h>

// Problem constants
#define CB  2
#define CS  2048
#define CE  1024
#define CH  16
#define CHD 64

// Scratch (no cudaMalloc allowed)
__device__ __half g_qkvh[(size_t)CB * CS * 3 * CE];  // QKV output, fp16 (Q pre-scaled)
__device__ __half g_ctxh[(size_t)CB * CS * CE];      // attention output, fp16
__device__ __half g_qh  [(size_t)CB * CS * CE];      // query, fp16
__device__ __half g_wqh [(size_t)3 * CE * CE];       // qkv_w, fp16
__device__ __half g_woh [(size_t)CE * CE];           // out_w, fp16

// ---------------------------------------------------------------------------
// helpers (plain sm_80-era PTX; no 'a'-suffix features)
// ---------------------------------------------------------------------------
__device__ __forceinline__ uint32_t smem_u32(const void* p) {
    uint32_t a;
    asm("{ .reg .u64 t; cvta.to.shared.u64 t, %1; cvt.u32.u64 %0, t; }"
        : "=r"(a) : "l"(p));
    return a;
}

__device__ __forceinline__ uint32_t f2h2(float lo, float hi) {
    __half2 v = __floats2half2_rn(lo, hi);
    return *(uint32_t*)&v;
}

// fp16: D += A(16x16) * B(16x8), fp32 accum
__device__ __forceinline__ void mma16(float* d, const uint32_t* a, const uint32_t* b) {
    asm volatile(
        "mma.sync.aligned.m16n8k16.row.col.f32.f16.f16.f32 "
        "{%0,%1,%2,%3}, {%4,%5,%6,%7}, {%8,%9}, {%0,%1,%2,%3};"
        : "+f"(d[0]), "+f"(d[1]), "+f"(d[2]), "+f"(d[3])
        : "r"(a[0]), "r"(a[1]), "r"(a[2]), "r"(a[3]), "r"(b[0]), "r"(b[1]));
}

__device__ __forceinline__ void ldsm_x4(uint32_t* r, uint32_t addr) {
    asm volatile("ldmatrix.sync.aligned.m8n8.x4.shared.b16 {%0,%1,%2,%3}, [%4];"
        : "=r"(r[0]), "=r"(r[1]), "=r"(r[2]), "=r"(r[3]) : "r"(addr));
}
__device__ __forceinline__ void ldsm_x4_t(uint32_t* r, uint32_t addr) {
    asm volatile("ldmatrix.sync.aligned.m8n8.x4.trans.shared.b16 {%0,%1,%2,%3}, [%4];"
        : "=r"(r[0]), "=r"(r[1]), "=r"(r[2]), "=r"(r[3]) : "r"(addr));
}

__device__ __forceinline__ void cp16(uint32_t saddr, const void* g) {
    asm volatile("cp.async.cg.shared.global [%0], [%1], 16;"
        :: "r"(saddr), "l"(g) : "memory");
}
__device__ __forceinline__ void cp_commit() {
    asm volatile("cp.async.commit_group;" ::: "memory");
}
template <int N>
__device__ __forceinline__ void cp_wait() {
    asm volatile("cp.async.wait_group %0;" :: "n"(N) : "memory");
}

// ---------------------------------------------------------------------------
// Elementwise fp32 -> fp16 pre-convert (8 elems/thread)
// ---------------------------------------------------------------------------
__global__ __launch_bounds__(256) void cvt_f16(const float* __restrict__ in,
                                               __half* __restrict__ out, int n8)
{
    int i = blockIdx.x * 256 + threadIdx.x;
    if (i < n8) {
        const float4* p = (const float4*)(in + (size_t)i * 8);
        float4 a = p[0], b = p[1];
        uint4 o;
        o.x = f2h2(a.x, a.y); o.y = f2h2(a.z, a.w);
        o.z = f2h2(b.x, b.y); o.w = f2h2(b.z, b.w);
        *(uint4*)(out + (size_t)i * 8) = o;
    }
}

// ===========================================================================
// fp16 GEMM: C[M,N] = A[M,K] * W[N,K]^T + bias[N]
// 128x128 CTA tile, BK=32, 256 threads (8 warps, 2m x 4n), warp tile 64x32.
// cp.async 3-stage; ldmatrix frags; m16n8k16 mma (fp32 accum).
// Row stride 80B (40 halves): ldmatrix phases conflict-free (20 banks, coprime).
// fp16_out=1: write fp16, scaling cols < CE by 0.125 (Q pre-scale for attention).
// ===========================================================================
#define GSTG   3
#define GROWB  80
#define GTILEB (128 * GROWB)              // 10240
#define GEMM_SMEM (GSTG * 2 * GTILEB)     // 61440

__global__ __launch_bounds__(256, 2) void hgemm_bias(
    const __half* __restrict__ A, const __half* __restrict__ W,
    const float* __restrict__ bias, void* __restrict__ Cv,
    int M, int N, int K, int fp16_out)
{
    extern __shared__ uint8_t gsm[];

    const int t    = threadIdx.x;
    const int wid  = t >> 5;
    const int lane = t & 31;
    const int g    = lane >> 2;
    const int tig  = lane & 3;
    const int wm   = (wid & 1) * 64;
    const int wn   = (wid >> 1) * 32;
    const int m0   = blockIdx.y * 128;
    const int n0   = blockIdx.x * 128;

    const uint32_t sa = smem_u32(gsm);
    const uint32_t sb = sa + GSTG * GTILEB;

    const int seg  = lane >> 3;
    const int r8   = lane & 7;
    const int arow = r8 + (seg & 1) * 8;   // A frag pattern
    const int ach  = seg >> 1;
    const int krow = r8 + (seg >> 1) * 8;  // B frag pattern
    const int kch  = seg & 1;

    float acc[4][4][4];
#pragma unroll
    for (int mf = 0; mf < 4; mf++)
#pragma unroll
        for (int nf = 0; nf < 4; nf++)
#pragma unroll
            for (int r = 0; r < 4; r++) acc[mf][nf][r] = 0.0f;

    const int NC = K >> 5;

    // 2 tiles x (128 rows x 4 chunks of 16B) = 1024 chunks; 4 per thread
    auto issue = [&](int st, int kc) {
#pragma unroll
        for (int i = 0; i < 2; i++) {
            int idx = t + i * 256;          // 0..511
            int row = idx >> 2;
            int ch  = idx & 3;
            uint32_t off = (uint32_t)(st * GTILEB + row * GROWB + ch * 16);
            cp16(sa + off, A + (size_t)(m0 + row) * K + kc * 32 + ch * 8);
            cp16(sb + off, W + (size_t)(n0 + row) * K + kc * 32 + ch * 8);
        }
        cp_commit();
    };

    issue(0, 0);
    issue(1, 1);

    for (int kc = 0; kc < NC; kc++) {
        if (kc < NC - 1) cp_wait<1>(); else cp_wait<0>();
        __syncthreads();
        if (kc + 2 < NC) issue((kc + 2) % GSTG, kc + 2);

        const int st = kc % GSTG;
        const uint32_t a0 = sa + st * GTILEB + (wm + arow) * GROWB + ach * 16;
        const uint32_t b0 = sb + st * GTILEB + (wn + krow) * GROWB + kch * 16;

#pragma unroll
        for (int kk = 0; kk < 2; kk++) {
            uint32_t a[4][4];
#pragma unroll
            for (int mf = 0; mf < 4; mf++)
                ldsm_x4(a[mf], a0 + mf * 16 * GROWB + kk * 32);
            uint32_t kb[2][4];
            ldsm_x4(kb[0], b0 + kk * 32);
            ldsm_x4(kb[1], b0 + 16 * GROWB + kk * 32);
#pragma unroll
            for (int n16 = 0; n16 < 2; n16++)
#pragma unroll
                for (int mf = 0; mf < 4; mf++) {
                    mma16(acc[mf][n16 * 2    ], a[mf], kb[n16]);
                    mma16(acc[mf][n16 * 2 + 1], a[mf], kb[n16] + 2);
                }
        }
    }

    // Epilogue. c0,c1 = row g cols (2tig,2tig+1); c2,c3 = row g+8.
    if (fp16_out) {
        __half* C = (__half*)Cv;
#pragma unroll
        for (int mf = 0; mf < 4; mf++)
#pragma unroll
            for (int nf = 0; nf < 4; nf++) {
                int row = m0 + wm + mf * 16 + g;
                int col = n0 + wn + nf * 8 + 2 * tig;
                float sc = (col < CE) ? 0.125f : 1.0f;   // Q pre-scale
                float2 bv = *(const float2*)(bias + col);
                uint32_t o0 = f2h2((acc[mf][nf][0] + bv.x) * sc,
                                   (acc[mf][nf][1] + bv.y) * sc);
                uint32_t o1 = f2h2((acc[mf][nf][2] + bv.x) * sc,
                                   (acc[mf][nf][3] + bv.y) * sc);
                *(uint32_t*)(C + (size_t)row * N + col)       = o0;
                *(uint32_t*)(C + (size_t)(row + 8) * N + col) = o1;
            }
    } else {
        float* C = (float*)Cv;
#pragma unroll
        for (int mf = 0; mf < 4; mf++)
#pragma unroll
            for (int nf = 0; nf < 4; nf++) {
                int row = m0 + wm + mf * 16 + g;
                int col = n0 + wn + nf * 8 + 2 * tig;
                float2 bv = *(const float2*)(bias + col);
                float2 o0 = make_float2(acc[mf][nf][0] + bv.x, acc[mf][nf][1] + bv.y);
                float2 o1 = make_float2(acc[mf][nf][2] + bv.x, acc[mf][nf][3] + bv.y);
                *(float2*)(C + (size_t)row * N + col)       = o0;
                *(float2*)(C + (size_t)(row + 8) * N + col) = o1;
            }
    }
}

// ===========================================================================
// Flash attention, fp16 mma.sync, fp16 source (g_qkvh; Q pre-scaled).
// CTA = 128 q x 64-key tiles, 128 threads = 4 warps x 32 q rows.
// cp.async double-buffered K/V; register-direct P (C-frag == A-frag layout);
// row stride 144B (proven conflict-free for ldmatrix).
// ===========================================================================
#define AROWB 144
#define ATTN_SMEM (128 * AROWB + 4 * 64 * AROWB)   // 55296 B

__global__ __launch_bounds__(128) void flash_attn_f16(
    const __half* __restrict__ qkvh,   // [B,S,3E] fp16
    __half* __restrict__ ctxh)         // [B,S,E]  fp16
{
    extern __shared__ uint8_t smb[];
    const uint32_t qsm = smem_u32(smb);
    const uint32_t ksm = qsm + 128 * AROWB;             // + buf * (64*AROWB)
    const uint32_t vsm = ksm + 2 * 64 * AROWB;          // + buf * (64*AROWB)
    const uint32_t KVB = 64 * AROWB;

    const int t    = threadIdx.x;
    const int wid  = t >> 5;
    const int lane = t & 31;
    const int g    = lane >> 2;
    const int tig  = lane & 3;
    const int wq   = wid * 32;

    const int q0 = blockIdx.x * 128;
    const int bh = blockIdx.y;
    const int b  = bh >> 4;
    const int h  = bh & 15;

    const size_t rs = 3 * CE;
    const __half* qb = qkvh + (size_t)b * CS * rs + h * CHD;
    const __half* kg = qb + CE;
    const __half* vg = qb + 2 * CE;

    // ldmatrix per-lane address components
    const int seg  = lane >> 3;
    const int r8   = lane & 7;
    const int arow = r8 + (seg & 1) * 8;   // A pattern (Q) and V-trans pattern
    const int ach  = seg >> 1;
    const int krow = r8 + (seg >> 1) * 8;  // K B-pattern
    const int kch  = seg & 1;

    // Loader: 16 rows x 8 chunks of 16B (8 halves)
    const int lr16 = t >> 3;   // 0..15
    const int lc8  = t & 7;    // 0..7

    auto issue_kv = [&](int buf, int kt) {
        const int k0 = kt * 64;
#pragma unroll
        for (int st = 0; st < 4; st++) {
            int row = st * 16 + lr16;
            uint32_t off = (uint32_t)(buf * KVB + row * AROWB + lc8 * 16);
            cp16(ksm + off, kg + (size_t)(k0 + row) * rs + lc8 * 8);
            cp16(vsm + off, vg + (size_t)(k0 + row) * rs + lc8 * 8);
        }
        cp_commit();
    };

    // ---- prologue: Q tile + K/V tile 0 as group 0 ----
#pragma unroll
    for (int st = 0; st < 8; st++) {
        int row = st * 16 + lr16;
        cp16(qsm + (uint32_t)(row * AROWB + lc8 * 16),
             qb + (size_t)(q0 + row) * rs + lc8 * 8);
    }
    issue_kv(0, 0);   // commits group 0 (Q + KV0)

    float m_i[2][2], l_i[2][2];
    float o[2][8][4];
#pragma unroll
    for (int mf = 0; mf < 2; mf++) {
        m_i[mf][0] = m_i[mf][1] = -3.0e38f;
        l_i[mf][0] = l_i[mf][1] = 0.0f;
#pragma unroll
        for (int nf = 0; nf < 8; nf++)
#pragma unroll
            for (int r = 0; r < 4; r++) o[mf][nf][r] = 0.0f;
    }

    const int NT = CS / 64;
    for (int kt = 0; kt < NT; kt++) {
        const int buf = kt & 1;
        __syncthreads();   // all warps done computing on buf^1 (prev-prev tile)
        if (kt + 1 < NT) {
            issue_kv(buf ^ 1, kt + 1);
            cp_wait<1>();
        } else {
            cp_wait<0>();
        }
        __syncthreads();   // tile kt data visible to all

        const uint32_t kbase = ksm + buf * KVB;
        const uint32_t vbase = vsm + buf * KVB;

        // ---- S = Q K^T  (32q x 64k per warp), 4 k16-steps ----
        float s[2][8][4];
#pragma unroll
        for (int mf = 0; mf < 2; mf++)
#pragma unroll
            for (int nf = 0; nf < 8; nf++)
#pragma unroll
                for (int r = 0; r < 4; r++) s[mf][nf][r] = 0.0f;

#pragma unroll
        for (int kk = 0; kk < 4; kk++) {
            uint32_t aq[2][4];
#pragma unroll
            for (int mf = 0; mf < 2; mf++)
                ldsm_x4(aq[mf], qsm + (uint32_t)((wq + mf * 16 + arow) * AROWB
                                                 + (kk * 2 + ach) * 16));
#pragma unroll
            for (int nfp = 0; nfp < 4; nfp++) {
                uint32_t kb[4];
                ldsm_x4(kb, kbase + (uint32_t)((nfp * 16 + krow) * AROWB
                                               + (kk * 2 + kch) * 16));
                mma16(s[0][nfp * 2    ], aq[0], kb);
                mma16(s[0][nfp * 2 + 1], aq[0], kb + 2);
                mma16(s[1][nfp * 2    ], aq[1], kb);
                mma16(s[1][nfp * 2 + 1], aq[1], kb + 2);
            }
        }

        // ---- online softmax -> P directly in A-frag registers ----
        uint32_t ph[2][4][4];
#pragma unroll
        for (int mf = 0; mf < 2; mf++) {
            float mx0 = -3.0e38f, mx1 = -3.0e38f;
#pragma unroll
            for (int nf = 0; nf < 8; nf++) {
                mx0 = fmaxf(mx0, fmaxf(s[mf][nf][0], s[mf][nf][1]));
                mx1 = fmaxf(mx1, fmaxf(s[mf][nf][2], s[mf][nf][3]));
            }
            mx0 = fmaxf(mx0, __shfl_xor_sync(0xffffffffu, mx0, 1));
            mx0 = fmaxf(mx0, __shfl_xor_sync(0xffffffffu, mx0, 2));
            mx1 = fmaxf(mx1, __shfl_xor_sync(0xffffffffu, mx1, 1));
            mx1 = fmaxf(mx1, __shfl_xor_sync(0xffffffffu, mx1, 2));

            float mn0 = fmaxf(m_i[mf][0], mx0);
            float mn1 = fmaxf(m_i[mf][1], mx1);
            float corr0 = __expf(m_i[mf][0] - mn0);
            float corr1 = __expf(m_i[mf][1] - mn1);
            float sum0 = 0.0f, sum1 = 0.0f;
#pragma unroll
            for (int nf = 0; nf < 8; nf++) {
                s[mf][nf][0] = __expf(s[mf][nf][0] - mn0);
                s[mf][nf][1] = __expf(s[mf][nf][1] - mn0);
                s[mf][nf][2] = __expf(s[mf][nf][2] - mn1);
                s[mf][nf][3] = __expf(s[mf][nf][3] - mn1);
                sum0 += s[mf][nf][0] + s[mf][nf][1];
                sum1 += s[mf][nf][2] + s[mf][nf][3];
            }
            sum0 += __shfl_xor_sync(0xffffffffu, sum0, 1);
            sum0 += __shfl_xor_sync(0xffffffffu, sum0, 2);
            sum1 += __shfl_xor_sync(0xffffffffu, sum1, 1);
            sum1 += __shfl_xor_sync(0xffffffffu, sum1, 2);

            l_i[mf][0] = l_i[mf][0] * corr0 + sum0;
            l_i[mf][1] = l_i[mf][1] * corr1 + sum1;
            m_i[mf][0] = mn0;
            m_i[mf][1] = mn1;
#pragma unroll
            for (int nf = 0; nf < 8; nf++) {
                o[mf][nf][0] *= corr0; o[mf][nf][1] *= corr0;
                o[mf][nf][2] *= corr1; o[mf][nf][3] *= corr1;
            }

            // C-frag -> A-frag: a0=row g k0-7, a1=row g+8 k0-7, a2/a3 = k8-15
#pragma unroll
            for (int j = 0; j < 4; j++) {
                ph[mf][j][0] = f2h2(s[mf][2 * j    ][0], s[mf][2 * j    ][1]);
                ph[mf][j][1] = f2h2(s[mf][2 * j    ][2], s[mf][2 * j    ][3]);
                ph[mf][j][2] = f2h2(s[mf][2 * j + 1][0], s[mf][2 * j + 1][1]);
                ph[mf][j][3] = f2h2(s[mf][2 * j + 1][2], s[mf][2 * j + 1][3]);
            }
        }

        // ---- O += P V  (A from regs; B via ldmatrix.trans on row-major V) ----
#pragma unroll
        for (int kk = 0; kk < 4; kk++) {
#pragma unroll
            for (int nfp = 0; nfp < 4; nfp++) {
                uint32_t vb[4];
                ldsm_x4_t(vb, vbase + (uint32_t)((kk * 16 + arow) * AROWB
                                                 + (nfp * 2 + ach) * 16));
                mma16(o[0][nfp * 2    ], ph[0][kk], vb);
                mma16(o[0][nfp * 2 + 1], ph[0][kk], vb + 2);
                mma16(o[1][nfp * 2    ], ph[1][kk], vb);
                mma16(o[1][nfp * 2 + 1], ph[1][kk], vb + 2);
            }
        }
    }

    // ---- Normalize + write ctx fp16 [b, q0+row, h*64 + col] ----
#pragma unroll
    for (int mf = 0; mf < 2; mf++) {
        float inv0 = 1.0f / l_i[mf][0];
        float inv1 = 1.0f / l_i[mf][1];
#pragma unroll
        for (int nf = 0; nf < 8; nf++) {
            int row = q0 + wq + mf * 16 + g;
            int col = h * CHD + nf * 8 + 2 * tig;
            *(uint32_t*)(ctxh + ((size_t)b * CS + row) * CE + col) =
                f2h2(o[mf][nf][0] * inv0, o[mf][nf][1] * inv0);
            *(uint32_t*)(ctxh + ((size_t)b * CS + row + 8) * CE + col) =
                f2h2(o[mf][nf][2] * inv1, o[mf][nf][3] * inv1);
        }
    }
}

// ---------------------------------------------------------------------------
extern "C" void kernel_launch(void* const* d_in, const int* in_sizes, int n_in,
                              void* d_out, int out_size)
{
    const float* query = (const float*)d_in[0];
    const float* qkv_w = (const float*)d_in[3];
    const float* qkv_b = (const float*)d_in[4];
    const float* out_w = (const float*)d_in[5];
    const float* out_b = (const float*)d_in[6];
    float* out = (float*)d_out;

    __half *qkvh = nullptr, *ctxh = nullptr, *qh = nullptr, *wqh = nullptr, *woh = nullptr;
    cudaGetSymbolAddress((void**)&qkvh, g_qkvh);
    cudaGetSymbolAddress((void**)&ctxh, g_ctxh);
    cudaGetSymbolAddress((void**)&qh,   g_qh);
    cudaGetSymbolAddress((void**)&wqh,  g_wqh);
    cudaGetSymbolAddress((void**)&woh,  g_woh);

    cudaFuncSetAttribute(flash_attn_f16,
                         cudaFuncAttributeMaxDynamicSharedMemorySize, ATTN_SMEM);
    cudaFuncSetAttribute(hgemm_bias,
                         cudaFuncAttributeMaxDynamicSharedMemorySize, GEMM_SMEM);

    // 0) Pre-convert operands to fp16
    cvt_f16<<<(CB * CS * CE / 8 + 255) / 256, 256>>>(query, qh, CB * CS * CE / 8);
    cvt_f16<<<(3 * CE * CE / 8 + 255) / 256, 256>>>(qkv_w, wqh, 3 * CE * CE / 8);
    cvt_f16<<<(CE * CE / 8 + 255) / 256, 256>>>(out_w, woh, CE * CE / 8);

    // 1) QKV projection -> fp16 (Q cols pre-scaled by 0.125)
    hgemm_bias<<<dim3(3 * CE / 128, CB * CS / 128), 256, GEMM_SMEM>>>(
        qh, wqh, qkv_b, qkvh, CB * CS, 3 * CE, CE, 1);

    // 2) Attention (fp16 in/out)
    flash_attn_f16<<<dim3(CS / 128, CB * CH), 128, ATTN_SMEM>>>(qkvh, ctxh);

    // 3) Output projection -> fp32 final
    hgemm_bias<<<dim3(CE / 128, CB * CS / 128), 256, GEMM_SMEM>>>(
        ctxh, woh, out_b, out, CB * CS, CE, CE, 0);
}

// round 12
// speedup vs baseline: 6.9184x; 1.0923x over previous
#include <cuda_runtime.h>
#include <cuda_fp16.h>
#include <cstdint>
#include <math.h>

// Problem constants
#define CB  2
#define CS  2048
#define CE  1024
#define CH  16
#define CHD 64

// Scratch (no cudaMalloc allowed)
__device__ __half g_qkvh[(size_t)CB * CS * 3 * CE];  // QKV output, fp16 (Q pre-scaled)
__device__ __half g_ctxh[(size_t)CB * CS * CE];      // attention output, fp16
__device__ __half g_qh  [(size_t)CB * CS * CE];      // query, fp16
__device__ __half g_wqh [(size_t)3 * CE * CE];       // qkv_w, fp16
__device__ __half g_woh [(size_t)CE * CE];           // out_w, fp16

// ---------------------------------------------------------------------------
// helpers (plain sm_80-era PTX; no 'a'-suffix features)
// ---------------------------------------------------------------------------
__device__ __forceinline__ uint32_t smem_u32(const void* p) {
    uint32_t a;
    asm("{ .reg .u64 t; cvta.to.shared.u64 t, %1; cvt.u32.u64 %0, t; }"
        : "=r"(a) : "l"(p));
    return a;
}

__device__ __forceinline__ uint32_t f2h2(float lo, float hi) {
    __half2 v = __floats2half2_rn(lo, hi);
    return *(uint32_t*)&v;
}

// fp16: D += A(16x16) * B(16x8), fp32 accum
__device__ __forceinline__ void mma16(float* d, const uint32_t* a, const uint32_t* b) {
    asm volatile(
        "mma.sync.aligned.m16n8k16.row.col.f32.f16.f16.f32 "
        "{%0,%1,%2,%3}, {%4,%5,%6,%7}, {%8,%9}, {%0,%1,%2,%3};"
        : "+f"(d[0]), "+f"(d[1]), "+f"(d[2]), "+f"(d[3])
        : "r"(a[0]), "r"(a[1]), "r"(a[2]), "r"(a[3]), "r"(b[0]), "r"(b[1]));
}

__device__ __forceinline__ void ldsm_x4(uint32_t* r, uint32_t addr) {
    asm volatile("ldmatrix.sync.aligned.m8n8.x4.shared.b16 {%0,%1,%2,%3}, [%4];"
        : "=r"(r[0]), "=r"(r[1]), "=r"(r[2]), "=r"(r[3]) : "r"(addr));
}
__device__ __forceinline__ void ldsm_x4_t(uint32_t* r, uint32_t addr) {
    asm volatile("ldmatrix.sync.aligned.m8n8.x4.trans.shared.b16 {%0,%1,%2,%3}, [%4];"
        : "=r"(r[0]), "=r"(r[1]), "=r"(r[2]), "=r"(r[3]) : "r"(addr));
}

__device__ __forceinline__ void cp16(uint32_t saddr, const void* g) {
    asm volatile("cp.async.cg.shared.global [%0], [%1], 16;"
        :: "r"(saddr), "l"(g) : "memory");
}
__device__ __forceinline__ void cp_commit() {
    asm volatile("cp.async.commit_group;" ::: "memory");
}
template <int N>
__device__ __forceinline__ void cp_wait() {
    asm volatile("cp.async.wait_group %0;" :: "n"(N) : "memory");
}

// ---------------------------------------------------------------------------
// Merged fp32 -> fp16 pre-convert for query / qkv_w / out_w (8 elems/thread)
// ---------------------------------------------------------------------------
#define N8_Q  (CB * CS * CE / 8)        // 524288
#define N8_WQ (3 * CE * CE / 8)         // 393216
#define N8_WO (CE * CE / 8)             // 131072

__global__ __launch_bounds__(256) void cvt_all(
    const float* __restrict__ q,  const float* __restrict__ wq,
    const float* __restrict__ wo, __half* __restrict__ qh,
    __half* __restrict__ wqh, __half* __restrict__ woh)
{
    int i = blockIdx.x * 256 + threadIdx.x;
    const float* in;
    __half* out;
    if (i < N8_Q)                { in = q;  out = qh; }
    else if (i < N8_Q + N8_WQ)   { i -= N8_Q;  in = wq; out = wqh; }
    else                         { i -= N8_Q + N8_WQ; in = wo; out = woh; }
    const float4* p = (const float4*)(in + (size_t)i * 8);
    float4 a = p[0], b = p[1];
    uint4 o;
    o.x = f2h2(a.x, a.y); o.y = f2h2(a.z, a.w);
    o.z = f2h2(b.x, b.y); o.w = f2h2(b.z, b.w);
    *(uint4*)(out + (size_t)i * 8) = o;
}

// ===========================================================================
// fp16 GEMM: C[M,N] = A[M,K] * W[N,K]^T + bias[N]
// 128x128 CTA tile, BK=64, 256 threads (8 warps, 2m x 4n), warp tile 64x32.
// cp.async 3-stage, ONE barrier per 64-deep chunk, 64 mma per warp per chunk.
// Row = 128B data + 16B pad (=144B): ldmatrix phases conflict-free (36r mod 32).
// fp16_out=1: write fp16, scaling cols < CE by 0.125*log2(e) (Q pre-scale,
// exp2-domain softmax downstream).
// ===========================================================================
#define GSTG   3
#define GROWB  144
#define GTILEB (128 * GROWB)              // 18432
#define GEMM_SMEM (GSTG * 2 * GTILEB)     // 110592
#define QSCALE 0.180336880f               // 0.125 * log2(e)

__global__ __launch_bounds__(256, 2) void hgemm_bias(
    const __half* __restrict__ A, const __half* __restrict__ W,
    const float* __restrict__ bias, void* __restrict__ Cv,
    int M, int N, int K, int fp16_out)
{
    extern __shared__ uint8_t gsm[];

    const int t    = threadIdx.x;
    const int wid  = t >> 5;
    const int lane = t & 31;
    const int g    = lane >> 2;
    const int tig  = lane & 3;
    const int wm   = (wid & 1) * 64;
    const int wn   = (wid >> 1) * 32;
    const int m0   = blockIdx.y * 128;
    const int n0   = blockIdx.x * 128;

    const uint32_t sa = smem_u32(gsm);
    const uint32_t sb = sa + GSTG * GTILEB;

    const int seg  = lane >> 3;
    const int r8   = lane & 7;
    const int arow = r8 + (seg & 1) * 8;   // A frag pattern
    const int ach  = seg >> 1;
    const int krow = r8 + (seg >> 1) * 8;  // B frag pattern
    const int kch  = seg & 1;

    float acc[4][4][4];
#pragma unroll
    for (int mf = 0; mf < 4; mf++)
#pragma unroll
        for (int nf = 0; nf < 4; nf++)
#pragma unroll
            for (int r = 0; r < 4; r++) acc[mf][nf][r] = 0.0f;

    const int NC = K >> 6;   // 16 for K=1024

    // per tile: 128 rows x 8 chunks of 16B = 1024 cps; 4/thread/tile
    auto issue = [&](int st, int kc) {
#pragma unroll
        for (int i = 0; i < 4; i++) {
            int idx = t + i * 256;          // 0..1023
            int row = idx >> 3;
            int ch  = idx & 7;
            uint32_t off = (uint32_t)(st * GTILEB + row * GROWB + ch * 16);
            cp16(sa + off, A + (size_t)(m0 + row) * K + kc * 64 + ch * 8);
            cp16(sb + off, W + (size_t)(n0 + row) * K + kc * 64 + ch * 8);
        }
        cp_commit();
    };

    issue(0, 0);
    issue(1, 1);

    for (int kc = 0; kc < NC; kc++) {
        if (kc < NC - 1) cp_wait<1>(); else cp_wait<0>();
        __syncthreads();
        if (kc + 2 < NC) issue((kc + 2) % GSTG, kc + 2);

        const int st = kc % GSTG;
        const uint32_t a0 = sa + st * GTILEB + (wm + arow) * GROWB + ach * 16;
        const uint32_t b0 = sb + st * GTILEB + (wn + krow) * GROWB + kch * 16;

#pragma unroll
        for (int kk = 0; kk < 4; kk++) {
            uint32_t a[4][4];
#pragma unroll
            for (int mf = 0; mf < 4; mf++)
                ldsm_x4(a[mf], a0 + mf * 16 * GROWB + kk * 32);
            uint32_t kb[2][4];
            ldsm_x4(kb[0], b0 + kk * 32);
            ldsm_x4(kb[1], b0 + 16 * GROWB + kk * 32);
#pragma unroll
            for (int n16 = 0; n16 < 2; n16++)
#pragma unroll
                for (int mf = 0; mf < 4; mf++) {
                    mma16(acc[mf][n16 * 2    ], a[mf], kb[n16]);
                    mma16(acc[mf][n16 * 2 + 1], a[mf], kb[n16] + 2);
                }
        }
    }

    // Epilogue. c0,c1 = row g cols (2tig,2tig+1); c2,c3 = row g+8.
    if (fp16_out) {
        __half* C = (__half*)Cv;
#pragma unroll
        for (int mf = 0; mf < 4; mf++)
#pragma unroll
            for (int nf = 0; nf < 4; nf++) {
                int row = m0 + wm + mf * 16 + g;
                int col = n0 + wn + nf * 8 + 2 * tig;
                float sc = (col < CE) ? QSCALE : 1.0f;   // Q pre-scale (exp2 domain)
                float2 bv = *(const float2*)(bias + col);
                uint32_t o0 = f2h2((acc[mf][nf][0] + bv.x) * sc,
                                   (acc[mf][nf][1] + bv.y) * sc);
                uint32_t o1 = f2h2((acc[mf][nf][2] + bv.x) * sc,
                                   (acc[mf][nf][3] + bv.y) * sc);
                *(uint32_t*)(C + (size_t)row * N + col)       = o0;
                *(uint32_t*)(C + (size_t)(row + 8) * N + col) = o1;
            }
    } else {
        float* C = (float*)Cv;
#pragma unroll
        for (int mf = 0; mf < 4; mf++)
#pragma unroll
            for (int nf = 0; nf < 4; nf++) {
                int row = m0 + wm + mf * 16 + g;
                int col = n0 + wn + nf * 8 + 2 * tig;
                float2 bv = *(const float2*)(bias + col);
                float2 o0 = make_float2(acc[mf][nf][0] + bv.x, acc[mf][nf][1] + bv.y);
                float2 o1 = make_float2(acc[mf][nf][2] + bv.x, acc[mf][nf][3] + bv.y);
                *(float2*)(C + (size_t)row * N + col)       = o0;
                *(float2*)(C + (size_t)(row + 8) * N + col) = o1;
            }
    }
}

// ===========================================================================
// Flash attention, fp16 mma.sync, fp16 source (g_qkvh; Q pre-scaled to exp2
// domain). CTA = 128 q x 64-key tiles, 128 threads = 4 warps x 32 q rows.
// 3-buffer cp.async KV ring, ONE barrier per tile; register-direct P;
// softmax in exp2 domain. Row stride 144B (ldmatrix conflict-free).
// ===========================================================================
#define AROWB 144
#define AQB   (128 * AROWB)               // 18432
#define AKVB  (64 * AROWB)                // 9216
#define ATTN_SMEM (AQB + 6 * AKVB)        // 73728

__global__ __launch_bounds__(128) void flash_attn_f16(
    const __half* __restrict__ qkvh,   // [B,S,3E] fp16
    __half* __restrict__ ctxh)         // [B,S,E]  fp16
{
    extern __shared__ uint8_t smb[];
    const uint32_t qsm = smem_u32(smb);
    const uint32_t ksm = qsm + AQB;        // + buf * AKVB  (3 bufs)
    const uint32_t vsm = ksm + 3 * AKVB;   // + buf * AKVB  (3 bufs)

    const int t    = threadIdx.x;
    const int wid  = t >> 5;
    const int lane = t & 31;
    const int g    = lane >> 2;
    const int tig  = lane & 3;
    const int wq   = wid * 32;

    const int q0 = blockIdx.x * 128;
    const int bh = blockIdx.y;
    const int b  = bh >> 4;
    const int h  = bh & 15;

    const size_t rs = 3 * CE;
    const __half* qb = qkvh + (size_t)b * CS * rs + h * CHD;
    const __half* kg = qb + CE;
    const __half* vg = qb + 2 * CE;

    // ldmatrix per-lane address components
    const int seg  = lane >> 3;
    const int r8   = lane & 7;
    const int arow = r8 + (seg & 1) * 8;   // A pattern (Q) and V-trans pattern
    const int ach  = seg >> 1;
    const int krow = r8 + (seg >> 1) * 8;  // K B-pattern
    const int kch  = seg & 1;

    // Loader: 16 rows x 8 chunks of 16B (8 halves)
    const int lr16 = t >> 3;   // 0..15
    const int lc8  = t & 7;    // 0..7

    auto issue_kv = [&](int buf, int kt) {
        const int k0 = kt * 64;
#pragma unroll
        for (int st = 0; st < 4; st++) {
            int row = st * 16 + lr16;
            uint32_t off = (uint32_t)(buf * AKVB + row * AROWB + lc8 * 16);
            cp16(ksm + off, kg + (size_t)(k0 + row) * rs + lc8 * 8);
            cp16(vsm + off, vg + (size_t)(k0 + row) * rs + lc8 * 8);
        }
        cp_commit();
    };

    // ---- prologue: group0 = Q tile + KV tile 0; group1 = KV tile 1 ----
#pragma unroll
    for (int st = 0; st < 8; st++) {
        int row = st * 16 + lr16;
        cp16(qsm + (uint32_t)(row * AROWB + lc8 * 16),
             qb + (size_t)(q0 + row) * rs + lc8 * 8);
    }
    issue_kv(0, 0);      // commits Q + KV0 together
    issue_kv(1, 1);

    float m_i[2][2], l_i[2][2];
    float o[2][8][4];
#pragma unroll
    for (int mf = 0; mf < 2; mf++) {
        m_i[mf][0] = m_i[mf][1] = -3.0e38f;
        l_i[mf][0] = l_i[mf][1] = 0.0f;
#pragma unroll
        for (int nf = 0; nf < 8; nf++)
#pragma unroll
            for (int r = 0; r < 4; r++) o[mf][nf][r] = 0.0f;
    }

    const int NT = CS / 64;
    for (int kt = 0; kt < NT; kt++) {
        const int buf = kt % 3;
        if (kt < NT - 1) cp_wait<1>(); else cp_wait<0>();
        __syncthreads();               // tile kt visible; buf (kt+2)%3 free
        if (kt + 2 < NT) issue_kv((kt + 2) % 3, kt + 2);

        const uint32_t kbase = ksm + buf * AKVB;
        const uint32_t vbase = vsm + buf * AKVB;

        // ---- S = Q K^T  (32q x 64k per warp), 4 k16-steps ----
        float s[2][8][4];
#pragma unroll
        for (int mf = 0; mf < 2; mf++)
#pragma unroll
            for (int nf = 0; nf < 8; nf++)
#pragma unroll
                for (int r = 0; r < 4; r++) s[mf][nf][r] = 0.0f;

#pragma unroll
        for (int kk = 0; kk < 4; kk++) {
            uint32_t aq[2][4];
#pragma unroll
            for (int mf = 0; mf < 2; mf++)
                ldsm_x4(aq[mf], qsm + (uint32_t)((wq + mf * 16 + arow) * AROWB
                                                 + (kk * 2 + ach) * 16));
#pragma unroll
            for (int nfp = 0; nfp < 4; nfp++) {
                uint32_t kb[4];
                ldsm_x4(kb, kbase + (uint32_t)((nfp * 16 + krow) * AROWB
                                               + (kk * 2 + kch) * 16));
                mma16(s[0][nfp * 2    ], aq[0], kb);
                mma16(s[0][nfp * 2 + 1], aq[0], kb + 2);
                mma16(s[1][nfp * 2    ], aq[1], kb);
                mma16(s[1][nfp * 2 + 1], aq[1], kb + 2);
            }
        }

        // ---- online softmax (exp2 domain) -> P in A-frag registers ----
        uint32_t ph[2][4][4];
#pragma unroll
        for (int mf = 0; mf < 2; mf++) {
            float mx0 = -3.0e38f, mx1 = -3.0e38f;
#pragma unroll
            for (int nf = 0; nf < 8; nf++) {
                mx0 = fmaxf(mx0, fmaxf(s[mf][nf][0], s[mf][nf][1]));
                mx1 = fmaxf(mx1, fmaxf(s[mf][nf][2], s[mf][nf][3]));
            }
            mx0 = fmaxf(mx0, __shfl_xor_sync(0xffffffffu, mx0, 1));
            mx0 = fmaxf(mx0, __shfl_xor_sync(0xffffffffu, mx0, 2));
            mx1 = fmaxf(mx1, __shfl_xor_sync(0xffffffffu, mx1, 1));
            mx1 = fmaxf(mx1, __shfl_xor_sync(0xffffffffu, mx1, 2));

            float mn0 = fmaxf(m_i[mf][0], mx0);
            float mn1 = fmaxf(m_i[mf][1], mx1);
            float corr0 = exp2f(m_i[mf][0] - mn0);
            float corr1 = exp2f(m_i[mf][1] - mn1);
            float sum0 = 0.0f, sum1 = 0.0f;
#pragma unroll
            for (int nf = 0; nf < 8; nf++) {
                s[mf][nf][0] = exp2f(s[mf][nf][0] - mn0);
                s[mf][nf][1] = exp2f(s[mf][nf][1] - mn0);
                s[mf][nf][2] = exp2f(s[mf][nf][2] - mn1);
                s[mf][nf][3] = exp2f(s[mf][nf][3] - mn1);
                sum0 += s[mf][nf][0] + s[mf][nf][1];
                sum1 += s[mf][nf][2] + s[mf][nf][3];
            }
            sum0 += __shfl_xor_sync(0xffffffffu, sum0, 1);
            sum0 += __shfl_xor_sync(0xffffffffu, sum0, 2);
            sum1 += __shfl_xor_sync(0xffffffffu, sum1, 1);
            sum1 += __shfl_xor_sync(0xffffffffu, sum1, 2);

            l_i[mf][0] = l_i[mf][0] * corr0 + sum0;
            l_i[mf][1] = l_i[mf][1] * corr1 + sum1;
            m_i[mf][0] = mn0;
            m_i[mf][1] = mn1;
#pragma unroll
            for (int nf = 0; nf < 8; nf++) {
                o[mf][nf][0] *= corr0; o[mf][nf][1] *= corr0;
                o[mf][nf][2] *= corr1; o[mf][nf][3] *= corr1;
            }

            // C-frag -> A-frag: a0=row g k0-7, a1=row g+8 k0-7, a2/a3 = k8-15
#pragma unroll
            for (int j = 0; j < 4; j++) {
                ph[mf][j][0] = f2h2(s[mf][2 * j    ][0], s[mf][2 * j    ][1]);
                ph[mf][j][1] = f2h2(s[mf][2 * j    ][2], s[mf][2 * j    ][3]);
                ph[mf][j][2] = f2h2(s[mf][2 * j + 1][0], s[mf][2 * j + 1][1]);
                ph[mf][j][3] = f2h2(s[mf][2 * j + 1][2], s[mf][2 * j + 1][3]);
            }
        }

        // ---- O += P V  (A from regs; B via ldmatrix.trans on row-major V) ----
#pragma unroll
        for (int kk = 0; kk < 4; kk++) {
#pragma unroll
            for (int nfp = 0; nfp < 4; nfp++) {
                uint32_t vb[4];
                ldsm_x4_t(vb, vbase + (uint32_t)((kk * 16 + arow) * AROWB
                                                 + (nfp * 2 + ach) * 16));
                mma16(o[0][nfp * 2    ], ph[0][kk], vb);
                mma16(o[0][nfp * 2 + 1], ph[0][kk], vb + 2);
                mma16(o[1][nfp * 2    ], ph[1][kk], vb);
                mma16(o[1][nfp * 2 + 1], ph[1][kk], vb + 2);
            }
        }
    }

    // ---- Normalize + write ctx fp16 [b, q0+row, h*64 + col] ----
#pragma unroll
    for (int mf = 0; mf < 2; mf++) {
        float inv0 = 1.0f / l_i[mf][0];
        float inv1 = 1.0f / l_i[mf][1];
#pragma unroll
        for (int nf = 0; nf < 8; nf++) {
            int row = q0 + wq + mf * 16 + g;
            int col = h * CHD + nf * 8 + 2 * tig;
            *(uint32_t*)(ctxh + ((size_t)b * CS + row) * CE + col) =
                f2h2(o[mf][nf][0] * inv0, o[mf][nf][1] * inv0);
            *(uint32_t*)(ctxh + ((size_t)b * CS + row + 8) * CE + col) =
                f2h2(o[mf][nf][2] * inv1, o[mf][nf][3] * inv1);
        }
    }
}

// ---------------------------------------------------------------------------
extern "C" void kernel_launch(void* const* d_in, const int* in_sizes, int n_in,
                              void* d_out, int out_size)
{
    const float* query = (const float*)d_in[0];
    const float* qkv_w = (const float*)d_in[3];
    const float* qkv_b = (const float*)d_in[4];
    const float* out_w = (const float*)d_in[5];
    const float* out_b = (const float*)d_in[6];
    float* out = (float*)d_out;

    __half *qkvh = nullptr, *ctxh = nullptr, *qh = nullptr, *wqh = nullptr, *woh = nullptr;
    cudaGetSymbolAddress((void**)&qkvh, g_qkvh);
    cudaGetSymbolAddress((void**)&ctxh, g_ctxh);
    cudaGetSymbolAddress((void**)&qh,   g_qh);
    cudaGetSymbolAddress((void**)&wqh,  g_wqh);
    cudaGetSymbolAddress((void**)&woh,  g_woh);

    cudaFuncSetAttribute(flash_attn_f16,
                         cudaFuncAttributeMaxDynamicSharedMemorySize, ATTN_SMEM);
    cudaFuncSetAttribute(hgemm_bias,
                         cudaFuncAttributeMaxDynamicSharedMemorySize, GEMM_SMEM);

    // 0) Pre-convert operands to fp16 (single launch)
    cvt_all<<<(N8_Q + N8_WQ + N8_WO) / 256, 256>>>(query, qkv_w, out_w, qh, wqh, woh);

    // 1) QKV projection -> fp16 (Q cols pre-scaled by 0.125*log2e)
    hgemm_bias<<<dim3(3 * CE / 128, CB * CS / 128), 256, GEMM_SMEM>>>(
        qh, wqh, qkv_b, qkvh, CB * CS, 3 * CE, CE, 1);

    // 2) Attention (fp16 in/out, exp2-domain softmax)
    flash_attn_f16<<<dim3(CS / 128, CB * CH), 128, ATTN_SMEM>>>(qkvh, ctxh);

    // 3) Output projection -> fp32 final
    hgemm_bias<<<dim3(CE / 128, CB * CS / 128), 256, GEMM_SMEM>>>(
        ctxh, woh, out_b, out, CB * CS, CE, CE, 0);
}

// round 14
// speedup vs baseline: 7.0412x; 1.0177x over previous
#include <cuda_runtime.h>
#include <cuda_fp16.h>
#include <cstdint>
#include <math.h>

// Problem constants
#define CB  2
#define CS  2048
#define CE  1024
#define CH  16
#define CHD 64

// Scratch (no cudaMalloc allowed)
__device__ __half g_qkvh[(size_t)CB * CS * 3 * CE];  // QKV output, fp16 (Q pre-scaled)
__device__ __half g_ctxh[(size_t)CB * CS * CE];      // attention output, fp16
__device__ __half g_qh  [(size_t)CB * CS * CE];      // query, fp16
__device__ __half g_wqh [(size_t)3 * CE * CE];       // qkv_w, fp16
__device__ __half g_woh [(size_t)CE * CE];           // out_w, fp16

// ---------------------------------------------------------------------------
// helpers (plain sm_80-era PTX; no 'a'-suffix features)
// ---------------------------------------------------------------------------
__device__ __forceinline__ uint32_t smem_u32(const void* p) {
    uint32_t a;
    asm("{ .reg .u64 t; cvta.to.shared.u64 t, %1; cvt.u32.u64 %0, t; }"
        : "=r"(a) : "l"(p));
    return a;
}

__device__ __forceinline__ uint32_t f2h2(float lo, float hi) {
    __half2 v = __floats2half2_rn(lo, hi);
    return *(uint32_t*)&v;
}

// fp16: D += A(16x16) * B(16x8), fp32 accum
__device__ __forceinline__ void mma16(float* d, const uint32_t* a, const uint32_t* b) {
    asm volatile(
        "mma.sync.aligned.m16n8k16.row.col.f32.f16.f16.f32 "
        "{%0,%1,%2,%3}, {%4,%5,%6,%7}, {%8,%9}, {%0,%1,%2,%3};"
        : "+f"(d[0]), "+f"(d[1]), "+f"(d[2]), "+f"(d[3])
        : "r"(a[0]), "r"(a[1]), "r"(a[2]), "r"(a[3]), "r"(b[0]), "r"(b[1]));
}

__device__ __forceinline__ void ldsm_x4(uint32_t* r, uint32_t addr) {
    asm volatile("ldmatrix.sync.aligned.m8n8.x4.shared.b16 {%0,%1,%2,%3}, [%4];"
        : "=r"(r[0]), "=r"(r[1]), "=r"(r[2]), "=r"(r[3]) : "r"(addr));
}
__device__ __forceinline__ void ldsm_x4_t(uint32_t* r, uint32_t addr) {
    asm volatile("ldmatrix.sync.aligned.m8n8.x4.trans.shared.b16 {%0,%1,%2,%3}, [%4];"
        : "=r"(r[0]), "=r"(r[1]), "=r"(r[2]), "=r"(r[3]) : "r"(addr));
}

__device__ __forceinline__ void cp16(uint32_t saddr, const void* g) {
    asm volatile("cp.async.cg.shared.global [%0], [%1], 16;"
        :: "r"(saddr), "l"(g) : "memory");
}
__device__ __forceinline__ void cp_commit() {
    asm volatile("cp.async.commit_group;" ::: "memory");
}
template <int N>
__device__ __forceinline__ void cp_wait() {
    asm volatile("cp.async.wait_group %0;" :: "n"(N) : "memory");
}

// ---------------------------------------------------------------------------
// Merged fp32 -> fp16 pre-convert for query / qkv_w / out_w (8 elems/thread)
// ---------------------------------------------------------------------------
#define N8_Q  (CB * CS * CE / 8)        // 524288
#define N8_WQ (3 * CE * CE / 8)         // 393216
#define N8_WO (CE * CE / 8)             // 131072

__global__ __launch_bounds__(256) void cvt_all(
    const float* __restrict__ q,  const float* __restrict__ wq,
    const float* __restrict__ wo, __half* __restrict__ qh,
    __half* __restrict__ wqh, __half* __restrict__ woh)
{
    int i = blockIdx.x * 256 + threadIdx.x;
    const float* in;
    __half* out;
    if (i < N8_Q)                { in = q;  out = qh; }
    else if (i < N8_Q + N8_WQ)   { i -= N8_Q;  in = wq; out = wqh; }
    else                         { i -= N8_Q + N8_WQ; in = wo; out = woh; }
    const float4* p = (const float4*)(in + (size_t)i * 8);
    float4 a = p[0], b = p[1];
    uint4 o;
    o.x = f2h2(a.x, a.y); o.y = f2h2(a.z, a.w);
    o.z = f2h2(b.x, b.y); o.w = f2h2(b.z, b.w);
    *(uint4*)(out + (size_t)i * 8) = o;
}

// ===========================================================================
// fp16 GEMM: C[M,N] = A[M,K] * W[N,K]^T + bias[N]
// 128x128 CTA tile, BK=64, 256 threads (8 warps, 2m x 4n), warp tile 64x32.
// cp.async 3-stage, ONE barrier per 64-deep chunk, 64 mma per warp per chunk.
// Row = 128B data + 16B pad (=144B): ldmatrix phases conflict-free.
// fp16_out=1: write fp16, scaling cols < CE by 0.125*log2(e).
// ===========================================================================
#define GSTG   3
#define GROWB  144
#define GTILEB (128 * GROWB)              // 18432
#define GEMM_SMEM (GSTG * 2 * GTILEB)     // 110592
#define QSCALE 0.180336880f               // 0.125 * log2(e)

__global__ __launch_bounds__(256, 2) void hgemm_bias(
    const __half* __restrict__ A, const __half* __restrict__ W,
    const float* __restrict__ bias, void* __restrict__ Cv,
    int M, int N, int K, int fp16_out)
{
    extern __shared__ uint8_t gsm[];

    const int t    = threadIdx.x;
    const int wid  = t >> 5;
    const int lane = t & 31;
    const int g    = lane >> 2;
    const int tig  = lane & 3;
    const int wm   = (wid & 1) * 64;
    const int wn   = (wid >> 1) * 32;
    const int m0   = blockIdx.y * 128;
    const int n0   = blockIdx.x * 128;

    const uint32_t sa = smem_u32(gsm);
    const uint32_t sb = sa + GSTG * GTILEB;

    const int seg  = lane >> 3;
    const int r8   = lane & 7;
    const int arow = r8 + (seg & 1) * 8;   // A frag pattern
    const int ach  = seg >> 1;
    const int krow = r8 + (seg >> 1) * 8;  // B frag pattern
    const int kch  = seg & 1;

    float acc[4][4][4];
#pragma unroll
    for (int mf = 0; mf < 4; mf++)
#pragma unroll
        for (int nf = 0; nf < 4; nf++)
#pragma unroll
            for (int r = 0; r < 4; r++) acc[mf][nf][r] = 0.0f;

    const int NC = K >> 6;   // 16 for K=1024

    // per tile: 128 rows x 8 chunks of 16B = 1024 cps; 4/thread/tile
    auto issue = [&](int st, int kc) {
#pragma unroll
        for (int i = 0; i < 4; i++) {
            int idx = t + i * 256;          // 0..1023
            int row = idx >> 3;
            int ch  = idx & 7;
            uint32_t off = (uint32_t)(st * GTILEB + row * GROWB + ch * 16);
            cp16(sa + off, A + (size_t)(m0 + row) * K + kc * 64 + ch * 8);
            cp16(sb + off, W + (size_t)(n0 + row) * K + kc * 64 + ch * 8);
        }
        cp_commit();
    };

    issue(0, 0);
    issue(1, 1);

    for (int kc = 0; kc < NC; kc++) {
        if (kc < NC - 1) cp_wait<1>(); else cp_wait<0>();
        __syncthreads();
        if (kc + 2 < NC) issue((kc + 2) % GSTG, kc + 2);

        const int st = kc % GSTG;
        const uint32_t a0 = sa + st * GTILEB + (wm + arow) * GROWB + ach * 16;
        const uint32_t b0 = sb + st * GTILEB + (wn + krow) * GROWB + kch * 16;

#pragma unroll
        for (int kk = 0; kk < 4; kk++) {
            uint32_t a[4][4];
#pragma unroll
            for (int mf = 0; mf < 4; mf++)
                ldsm_x4(a[mf], a0 + mf * 16 * GROWB + kk * 32);
            uint32_t kb[2][4];
            ldsm_x4(kb[0], b0 + kk * 32);
            ldsm_x4(kb[1], b0 + 16 * GROWB + kk * 32);
#pragma unroll
            for (int n16 = 0; n16 < 2; n16++)
#pragma unroll
                for (int mf = 0; mf < 4; mf++) {
                    mma16(acc[mf][n16 * 2    ], a[mf], kb[n16]);
                    mma16(acc[mf][n16 * 2 + 1], a[mf], kb[n16] + 2);
                }
        }
    }

    // Epilogue. c0,c1 = row g cols (2tig,2tig+1); c2,c3 = row g+8.
    if (fp16_out) {
        __half* C = (__half*)Cv;
#pragma unroll
        for (int mf = 0; mf < 4; mf++)
#pragma unroll
            for (int nf = 0; nf < 4; nf++) {
                int row = m0 + wm + mf * 16 + g;
                int col = n0 + wn + nf * 8 + 2 * tig;
                float sc = (col < CE) ? QSCALE : 1.0f;   // Q pre-scale (exp2 domain)
                float2 bv = *(const float2*)(bias + col);
                uint32_t o0 = f2h2((acc[mf][nf][0] + bv.x) * sc,
                                   (acc[mf][nf][1] + bv.y) * sc);
                uint32_t o1 = f2h2((acc[mf][nf][2] + bv.x) * sc,
                                   (acc[mf][nf][3] + bv.y) * sc);
                *(uint32_t*)(C + (size_t)row * N + col)       = o0;
                *(uint32_t*)(C + (size_t)(row + 8) * N + col) = o1;
            }
    } else {
        float* C = (float*)Cv;
#pragma unroll
        for (int mf = 0; mf < 4; mf++)
#pragma unroll
            for (int nf = 0; nf < 4; nf++) {
                int row = m0 + wm + mf * 16 + g;
                int col = n0 + wn + nf * 8 + 2 * tig;
                float2 bv = *(const float2*)(bias + col);
                float2 o0 = make_float2(acc[mf][nf][0] + bv.x, acc[mf][nf][1] + bv.y);
                float2 o1 = make_float2(acc[mf][nf][2] + bv.x, acc[mf][nf][3] + bv.y);
                *(float2*)(C + (size_t)row * N + col)       = o0;
                *(float2*)(C + (size_t)(row + 8) * N + col) = o1;
            }
    }
}

// ===========================================================================
// Flash attention, fp16 mma.sync, fp16 source (g_qkvh; Q pre-scaled to exp2
// domain). CTA = 64 q x 64-key tiles, 128 threads = 4 warps x 16 q rows.
// 2-buffer cp.async KV ring, ONE barrier per tile; register-direct P;
// softmax in exp2 domain. smem 46 KB -> 4 CTAs/SM; grid 1024 -> 2 clean waves.
// ===========================================================================
#define AROWB 144
#define AQB   (64 * AROWB)                // 9216
#define AKVB  (64 * AROWB)                // 9216
#define ATTN_SMEM (AQB + 4 * AKVB)        // 46080

__global__ __launch_bounds__(128) void flash_attn_f16(
    const __half* __restrict__ qkvh,   // [B,S,3E] fp16
    __half* __restrict__ ctxh)         // [B,S,E]  fp16
{
    extern __shared__ uint8_t smb[];
    const uint32_t qsm = smem_u32(smb);
    const uint32_t ksm = qsm + AQB;        // + buf * AKVB  (2 bufs)
    const uint32_t vsm = ksm + 2 * AKVB;   // + buf * AKVB  (2 bufs)

    const int t    = threadIdx.x;
    const int wid  = t >> 5;
    const int lane = t & 31;
    const int g    = lane >> 2;
    const int tig  = lane & 3;
    const int wq   = wid * 16;             // warp's q-row base (16 rows/warp)

    const int q0 = blockIdx.x * 64;
    const int bh = blockIdx.y;
    const int b  = bh >> 4;
    const int h  = bh & 15;

    const size_t rs = 3 * CE;
    const __half* qb = qkvh + (size_t)b * CS * rs + h * CHD;
    const __half* kg = qb + CE;
    const __half* vg = qb + 2 * CE;

    // ldmatrix per-lane address components
    const int seg  = lane >> 3;
    const int r8   = lane & 7;
    const int arow = r8 + (seg & 1) * 8;   // A pattern (Q) and V-trans pattern
    const int ach  = seg >> 1;
    const int krow = r8 + (seg >> 1) * 8;  // K B-pattern
    const int kch  = seg & 1;

    // Loader: 16 rows x 8 chunks of 16B (8 halves)
    const int lr16 = t >> 3;   // 0..15
    const int lc8  = t & 7;    // 0..7

    auto issue_kv = [&](int buf, int kt) {
        const int k0 = kt * 64;
#pragma unroll
        for (int st = 0; st < 4; st++) {
            int row = st * 16 + lr16;
            uint32_t off = (uint32_t)(buf * AKVB + row * AROWB + lc8 * 16);
            cp16(ksm + off, kg + (size_t)(k0 + row) * rs + lc8 * 8);
            cp16(vsm + off, vg + (size_t)(k0 + row) * rs + lc8 * 8);
        }
        cp_commit();
    };

    // ---- prologue: group0 = Q tile (64 rows) + KV tile 0 ----
#pragma unroll
    for (int st = 0; st < 4; st++) {
        int row = st * 16 + lr16;
        cp16(qsm + (uint32_t)(row * AROWB + lc8 * 16),
             qb + (size_t)(q0 + row) * rs + lc8 * 8);
    }
    issue_kv(0, 0);      // commits Q + KV0 together

    float m_i[2] = {-3.0e38f, -3.0e38f};
    float l_i[2] = {0.0f, 0.0f};
    float o[8][4];
#pragma unroll
    for (int nf = 0; nf < 8; nf++)
#pragma unroll
        for (int r = 0; r < 4; r++) o[nf][r] = 0.0f;

    const int NT = CS / 64;
    for (int kt = 0; kt < NT; kt++) {
        const int buf = kt & 1;
        cp_wait<0>();
        __syncthreads();               // tile kt visible; other buf free
        if (kt + 1 < NT) issue_kv(buf ^ 1, kt + 1);

        const uint32_t kbase = ksm + buf * AKVB;
        const uint32_t vbase = vsm + buf * AKVB;

        // ---- S = Q K^T  (16q x 64k per warp), 4 k16-steps ----
        float s[8][4];
#pragma unroll
        for (int nf = 0; nf < 8; nf++)
#pragma unroll
            for (int r = 0; r < 4; r++) s[nf][r] = 0.0f;

#pragma unroll
        for (int kk = 0; kk < 4; kk++) {
            uint32_t aq[4];
            ldsm_x4(aq, qsm + (uint32_t)((wq + arow) * AROWB + (kk * 2 + ach) * 16));
#pragma unroll
            for (int nfp = 0; nfp < 4; nfp++) {
                uint32_t kb[4];
                ldsm_x4(kb, kbase + (uint32_t)((nfp * 16 + krow) * AROWB
                                               + (kk * 2 + kch) * 16));
                mma16(s[nfp * 2    ], aq, kb);
                mma16(s[nfp * 2 + 1], aq, kb + 2);
            }
        }

        // ---- online softmax (exp2 domain) -> P in A-frag registers ----
        float mx0 = -3.0e38f, mx1 = -3.0e38f;
#pragma unroll
        for (int nf = 0; nf < 8; nf++) {
            mx0 = fmaxf(mx0, fmaxf(s[nf][0], s[nf][1]));
            mx1 = fmaxf(mx1, fmaxf(s[nf][2], s[nf][3]));
        }
        mx0 = fmaxf(mx0, __shfl_xor_sync(0xffffffffu, mx0, 1));
        mx0 = fmaxf(mx0, __shfl_xor_sync(0xffffffffu, mx0, 2));
        mx1 = fmaxf(mx1, __shfl_xor_sync(0xffffffffu, mx1, 1));
        mx1 = fmaxf(mx1, __shfl_xor_sync(0xffffffffu, mx1, 2));

        float mn0 = fmaxf(m_i[0], mx0);
        float mn1 = fmaxf(m_i[1], mx1);
        float corr0 = exp2f(m_i[0] - mn0);
        float corr1 = exp2f(m_i[1] - mn1);
        float sum0 = 0.0f, sum1 = 0.0f;
#pragma unroll
        for (int nf = 0; nf < 8; nf++) {
            s[nf][0] = exp2f(s[nf][0] - mn0);
            s[nf][1] = exp2f(s[nf][1] - mn0);
            s[nf][2] = exp2f(s[nf][2] - mn1);
            s[nf][3] = exp2f(s[nf][3] - mn1);
            sum0 += s[nf][0] + s[nf][1];
            sum1 += s[nf][2] + s[nf][3];
        }
        sum0 += __shfl_xor_sync(0xffffffffu, sum0, 1);
        sum0 += __shfl_xor_sync(0xffffffffu, sum0, 2);
        sum1 += __shfl_xor_sync(0xffffffffu, sum1, 1);
        sum1 += __shfl_xor_sync(0xffffffffu, sum1, 2);

        l_i[0] = l_i[0] * corr0 + sum0;
        l_i[1] = l_i[1] * corr1 + sum1;
        m_i[0] = mn0;
        m_i[1] = mn1;
#pragma unroll
        for (int nf = 0; nf < 8; nf++) {
            o[nf][0] *= corr0; o[nf][1] *= corr0;
            o[nf][2] *= corr1; o[nf][3] *= corr1;
        }

        // C-frag -> A-frag: a0=row g k0-7, a1=row g+8 k0-7, a2/a3 = k8-15
        uint32_t ph[4][4];
#pragma unroll
        for (int j = 0; j < 4; j++) {
            ph[j][0] = f2h2(s[2 * j    ][0], s[2 * j    ][1]);
            ph[j][1] = f2h2(s[2 * j    ][2], s[2 * j    ][3]);
            ph[j][2] = f2h2(s[2 * j + 1][0], s[2 * j + 1][1]);
            ph[j][3] = f2h2(s[2 * j + 1][2], s[2 * j + 1][3]);
        }

        // ---- O += P V  (A from regs; B via ldmatrix.trans on row-major V) ----
#pragma unroll
        for (int kk = 0; kk < 4; kk++) {
#pragma unroll
            for (int nfp = 0; nfp < 4; nfp++) {
                uint32_t vb[4];
                ldsm_x4_t(vb, vbase + (uint32_t)((kk * 16 + arow) * AROWB
                                                 + (nfp * 2 + ach) * 16));
                mma16(o[nfp * 2    ], ph[kk], vb);
                mma16(o[nfp * 2 + 1], ph[kk], vb + 2);
            }
        }
    }

    // ---- Normalize + write ctx fp16 [b, q0+row, h*64 + col] ----
    float inv0 = 1.0f / l_i[0];
    float inv1 = 1.0f / l_i[1];
#pragma unroll
    for (int nf = 0; nf < 8; nf++) {
        int row = q0 + wq + g;
        int col = h * CHD + nf * 8 + 2 * tig;
        *(uint32_t*)(ctxh + ((size_t)b * CS + row) * CE + col) =
            f2h2(o[nf][0] * inv0, o[nf][1] * inv0);
        *(uint32_t*)(ctxh + ((size_t)b * CS + row + 8) * CE + col) =
            f2h2(o[nf][2] * inv1, o[nf][3] * inv1);
    }
}

// ---------------------------------------------------------------------------
extern "C" void kernel_launch(void* const* d_in, const int* in_sizes, int n_in,
                              void* d_out, int out_size)
{
    const float* query = (const float*)d_in[0];
    const float* qkv_w = (const float*)d_in[3];
    const float* qkv_b = (const float*)d_in[4];
    const float* out_w = (const float*)d_in[5];
    const float* out_b = (const float*)d_in[6];
    float* out = (float*)d_out;

    __half *qkvh = nullptr, *ctxh = nullptr, *qh = nullptr, *wqh = nullptr, *woh = nullptr;
    cudaGetSymbolAddress((void**)&qkvh, g_qkvh);
    cudaGetSymbolAddress((void**)&ctxh, g_ctxh);
    cudaGetSymbolAddress((void**)&qh,   g_qh);
    cudaGetSymbolAddress((void**)&wqh,  g_wqh);
    cudaGetSymbolAddress((void**)&woh,  g_woh);

    cudaFuncSetAttribute(flash_attn_f16,
                         cudaFuncAttributeMaxDynamicSharedMemorySize, ATTN_SMEM);
    cudaFuncSetAttribute(hgemm_bias,
                         cudaFuncAttributeMaxDynamicSharedMemorySize, GEMM_SMEM);

    // 0) Pre-convert operands to fp16 (single launch)
    cvt_all<<<(N8_Q + N8_WQ + N8_WO) / 256, 256>>>(query, qkv_w, out_w, qh, wqh, woh);

    // 1) QKV projection -> fp16 (Q cols pre-scaled by 0.125*log2e)
    hgemm_bias<<<dim3(3 * CE / 128, CB * CS / 128), 256, GEMM_SMEM>>>(
        qh, wqh, qkv_b, qkvh, CB * CS, 3 * CE, CE, 1);

    // 2) Attention: 32 q-tiles x (B*H)=32, 4 CTAs/SM, 2 waves
    flash_attn_f16<<<dim3(CS / 64, CB * CH), 128, ATTN_SMEM>>>(qkvh, ctxh);

    // 3) Output projection -> fp32 final
    hgemm_bias<<<dim3(CE / 128, CB * CS / 128), 256, GEMM_SMEM>>>(
        ctxh, woh, out_b, out, CB * CS, CE, CE, 0);
}